// round 9
// baseline (speedup 1.0000x reference)
#include <cuda_runtime.h>
#include <cuda_fp16.h>

// Problem dims (fixed)
#define B_      8
#define N_      1024
#define IN_DIM  256
#define OUT_DIM 256
#define H_      8
#define D_      32
#define ROWS_   (B_ * N_)          // 8192

// ---------------- static device scratch (no allocations allowed) ----------------
__device__ float           g_inputs[(size_t)ROWS_ * OUT_DIM];   // 32MB: X@W, [row][h*32+d]
__device__ __half          g_vhalf[(size_t)B_ * H_ * N_ * D_];  // 16MB: fp16 V, head-major
__device__ float           g_self[B_ * H_ * N_];                // [b][h][n]
__device__ float           g_neigh[B_ * H_ * N_];               // [b][h][n]
__device__ unsigned short  g_idx[(size_t)ROWS_ * N_];           // 16MB CSR cols (fixed stride)
__device__ int             g_cnt[ROWS_];

// ======================= K1: fused SGEMM (inputs = X@W) + CSR build =======================
// blocks [0,128): gemm 128x128 tiles; blocks [128,1152): adjacency->CSR (8 rows each).
// gemm CTAs first in bid order -> start immediately; DRAM-bound csr CTAs backfill
// the 20 gemm-free SMs and co-resident slots, hiding csr inside gemm's compute time.
#define BM 128
#define BN 128
#define BK 16

__global__ __launch_bounds__(256) void k_fused(const float* __restrict__ X,
                                               const float* __restrict__ W,
                                               const float* __restrict__ A) {
    if (blockIdx.x < 128) {
        // ---------------- GEMM branch ----------------
        __shared__ float As[BK][BM];   // transposed A tile
        __shared__ float Bs[BK][BN];

        const int tid  = threadIdx.x;
        const int row0 = (blockIdx.x >> 1) * BM;
        const int col0 = (blockIdx.x & 1) * BN;
        const int tr   = (tid >> 4) * 8;
        const int tc   = (tid & 15) * 8;

        float acc[8][8];
#pragma unroll
        for (int i = 0; i < 8; i++)
#pragma unroll
            for (int j = 0; j < 8; j++) acc[i][j] = 0.f;

        for (int k0 = 0; k0 < IN_DIM; k0 += BK) {
#pragma unroll
            for (int l = 0; l < 2; l++) {
                int f  = tid * 2 + l;
                int r  = f >> 2;
                int c4 = (f & 3) * 4;
                float4 v = *(const float4*)(X + (size_t)(row0 + r) * IN_DIM + k0 + c4);
                As[c4 + 0][r] = v.x;
                As[c4 + 1][r] = v.y;
                As[c4 + 2][r] = v.z;
                As[c4 + 3][r] = v.w;
            }
#pragma unroll
            for (int l = 0; l < 2; l++) {
                int f  = tid * 2 + l;
                int r  = f >> 5;
                int c4 = (f & 31) * 4;
                float4 v = *(const float4*)(W + (size_t)(k0 + r) * OUT_DIM + col0 + c4);
                *(float4*)&Bs[r][c4] = v;
            }
            __syncthreads();

#pragma unroll
            for (int k = 0; k < BK; k++) {
                float a[8], b[8];
                *(float4*)&a[0] = *(const float4*)&As[k][tr];
                *(float4*)&a[4] = *(const float4*)&As[k][tr + 4];
                *(float4*)&b[0] = *(const float4*)&Bs[k][tc];
                *(float4*)&b[4] = *(const float4*)&Bs[k][tc + 4];
#pragma unroll
                for (int i = 0; i < 8; i++)
#pragma unroll
                    for (int j = 0; j < 8; j++) acc[i][j] = fmaf(a[i], b[j], acc[i][j]);
            }
            __syncthreads();
        }

#pragma unroll
        for (int i = 0; i < 8; i++) {
            float* dst = g_inputs + (size_t)(row0 + tr + i) * OUT_DIM + col0 + tc;
            float4 v0 = {acc[i][0], acc[i][1], acc[i][2], acc[i][3]};
            float4 v1 = {acc[i][4], acc[i][5], acc[i][6], acc[i][7]};
            *(float4*)(dst)     = v0;
            *(float4*)(dst + 4) = v1;
        }
    } else {
        // ---------------- CSR branch (warp per row; A entries exactly 0.0/1.0) ----------------
        int warp = threadIdx.x >> 5;
        int lane = threadIdx.x & 31;
        int row  = (blockIdx.x - 128) * 8 + warp;

        const float* Arow = A + (size_t)row * N_;
        unsigned short* out = g_idx + (size_t)row * N_;

        int base = 0;
#pragma unroll
        for (int it = 0; it < 8; it++) {
            float4 v = *(const float4*)(Arow + it * 128 + lane * 4);
            float vals[4] = {v.x, v.y, v.z, v.w};
#pragma unroll
            for (int e = 0; e < 4; e++) {
                bool nz = (vals[e] != 0.f);
                unsigned mask = __ballot_sync(0xffffffffu, nz);
                if (nz) {
                    int pos = base + __popc(mask & ((1u << lane) - 1u));
                    out[pos] = (unsigned short)(it * 128 + lane * 4 + e);
                }
                base += __popc(mask);
            }
        }
        if (lane == 0) g_cnt[row] = base;
    }
}

// ======================= K2: attention scores + fp16 V pre-convert =======================
// gid -> (h = gid>>13, row = gid&8191): warps write contiguous per-head planes.
__global__ __launch_bounds__(256) void k_scores(const float* __restrict__ fc1,
                                                const float* __restrict__ fc2) {
    __shared__ float f1[H_ * D_];
    __shared__ float f2[H_ * D_];
    int t = threadIdx.x;
    f1[t] = fc1[t];
    f2[t] = fc2[t];
    __syncthreads();

    int gid = blockIdx.x * 256 + t;
    int h   = gid >> 13;
    int row = gid & (ROWS_ - 1);
    int b_  = row >> 10;
    int n   = row & (N_ - 1);

    const float* ip = g_inputs + (size_t)row * OUT_DIM + h * D_;
    __half* vdst = g_vhalf + ((size_t)(b_ * H_ + h) * N_ + n) * D_;

    float s1 = 0.f, s2 = 0.f;
#pragma unroll
    for (int i = 0; i < D_; i += 4) {
        float4 v = *(const float4*)(ip + i);
        float4 a = *(const float4*)(f1 + h * D_ + i);
        float4 bq = *(const float4*)(f2 + h * D_ + i);
        s1 += v.x * a.x + v.y * a.y + v.z * a.z + v.w * a.w;
        s2 += v.x * bq.x + v.y * bq.y + v.z * bq.z + v.w * bq.w;
        __half2 h01 = __floats2half2_rn(v.x, v.y);
        __half2 h23 = __floats2half2_rn(v.z, v.w);
        uint2 pk;
        pk.x = *(unsigned*)&h01;
        pk.y = *(unsigned*)&h23;
        *(uint2*)(vdst + i) = pk;
    }
    g_self [(b_ * H_ + h) * N_ + n] = s1;
    g_neigh[(b_ * H_ + h) * N_ + n] = s2;
}

// ======================= K3: sparse softmax-attention aggregation =======================
// fp16 V tile (64KB, pure copy from g_vhalf) + fp32 neigh scores (4KB) = 68KB smem.
// 384 threads, 3 CTAs/SM -> 36 resident warps. Lane layout: g=lane>>3 picks 1-of-4
// edges per step, s=lane&7 -> dims [4s,4s+4). (p,m) travel in ONE shfl word.
#define RB 8   // row-blocks per (b,h) -> 128 rows per CTA, grid = 512 CTAs

__global__ __launch_bounds__(384, 3) void k_attn(float* __restrict__ out) {
    extern __shared__ char smraw[];
    __half* Vs = (__half*)smraw;                       // [1024][32] fp16
    float*  ns = (float*)(smraw + N_ * D_ * 2);        // [1024]

    const int b  = blockIdx.z;
    const int h  = blockIdx.y;
    const int rb = blockIdx.x;
    const int tid = threadIdx.x;

    // stage V (pure 64KB copy) + neigh scores
    {
        const uint4* vsrc = (const uint4*)(g_vhalf + (size_t)(b * H_ + h) * N_ * D_);
        uint4* vdst = (uint4*)Vs;
        for (int f = tid; f < N_ * D_ / 8; f += 384) vdst[f] = vsrc[f];
        const float* nsrc = g_neigh + (b * H_ + h) * N_;
        for (int m = tid; m < N_; m += 384) ns[m] = nsrc[m];
    }
    __syncthreads();

    const int warp = tid >> 5;
    const int lane = tid & 31;
    const int g    = lane >> 3;
    const int s    = lane & 7;
    const int rbase = rb * (N_ / RB);

    for (int n = rbase + warp; n < rbase + N_ / RB; n += 12) {
        const int row = b * N_ + n;
        const int nb  = g_cnt[row];
        const float self = g_self[(b * H_ + h) * N_ + n];
        const unsigned short* ip = g_idx + (size_t)row * N_;

        // ---- front: slots 2*lane, 2*lane+1 via one ushort2 load
        const ushort2 mm = *(const ushort2*)(ip + 2 * lane);
        const unsigned m0 = mm.x, m1 = mm.y;
        const bool a0 = (2 * lane < nb);
        const bool a1 = (2 * lane + 1 < nb);
        float p0 = 0.f, p1 = 0.f;
        if (a0) {
            float sc = self + ns[m0];
            sc = (sc >= 0.f) ? sc : 0.01f * sc;
            p0 = __expf(sc);
        }
        if (a1) {
            float sc = self + ns[m1];
            sc = (sc >= 0.f) ? sc : 0.01f * sc;
            p1 = __expf(sc);
        }
        float psum = p0 + p1;
        const unsigned pm0 = a0 ? ((__float_as_uint(p0) & ~1023u) | m0) : 0u;
        const unsigned pm1 = a1 ? ((__float_as_uint(p1) & ~1023u) | m1) : 0u;
        float4 acc = {0.f, 0.f, 0.f, 0.f};

        // ---- rare tail: nb > 64
        for (int base = 64; base < nb; base += 32) {
            unsigned mt = 0;
            float pt = 0.f;
            if (base + lane < nb) {
                mt = ip[base + lane];
                float sc = self + ns[mt];
                sc = (sc >= 0.f) ? sc : 0.01f * sc;
                pt = __expf(sc);
            }
            psum += pt;
            unsigned pmt = (__float_as_uint(pt) & ~1023u) | mt;
#pragma unroll
            for (int t = 0; t < 8; t++) {
                unsigned pmj = __shfl_sync(0xffffffffu, pmt, 4 * t + g);
                float    pj  = __uint_as_float(pmj);
                unsigned mj  = pmj & 1023u;
                uint2 hv = *(const uint2*)(Vs + (mj << 5) + (s << 2));
                float2 f01 = __half22float2(*(__half2*)&hv.x);
                float2 f23 = __half22float2(*(__half2*)&hv.y);
                acc.x = fmaf(pj, f01.x, acc.x);
                acc.y = fmaf(pj, f01.y, acc.y);
                acc.z = fmaf(pj, f23.x, acc.z);
                acc.w = fmaf(pj, f23.y, acc.w);
            }
        }

        // ---- main body: 16 fully-unrolled independent steps, one shfl each
#pragma unroll
        for (int t = 0; t < 8; t++) {
            unsigned pmj = __shfl_sync(0xffffffffu, pm0, 4 * t + g);
            float    pj  = __uint_as_float(pmj);
            unsigned mj  = pmj & 1023u;
            uint2 hv = *(const uint2*)(Vs + (mj << 5) + (s << 2));
            float2 f01 = __half22float2(*(__half2*)&hv.x);
            float2 f23 = __half22float2(*(__half2*)&hv.y);
            acc.x = fmaf(pj, f01.x, acc.x);
            acc.y = fmaf(pj, f01.y, acc.y);
            acc.z = fmaf(pj, f23.x, acc.z);
            acc.w = fmaf(pj, f23.y, acc.w);
        }
#pragma unroll
        for (int t = 0; t < 8; t++) {
            unsigned pmj = __shfl_sync(0xffffffffu, pm1, 4 * t + g);
            float    pj  = __uint_as_float(pmj);
            unsigned mj  = pmj & 1023u;
            uint2 hv = *(const uint2*)(Vs + (mj << 5) + (s << 2));
            float2 f01 = __half22float2(*(__half2*)&hv.x);
            float2 f23 = __half22float2(*(__half2*)&hv.y);
            acc.x = fmaf(pj, f01.x, acc.x);
            acc.y = fmaf(pj, f01.y, acc.y);
            acc.z = fmaf(pj, f23.x, acc.z);
            acc.w = fmaf(pj, f23.y, acc.w);
        }

        // reduce denominator over all 32 lanes
#pragma unroll
        for (int off = 16; off; off >>= 1) psum += __shfl_xor_sync(0xffffffffu, psum, off);
        // reduce acc across the 4 edge-groups (lane bits 3..4)
        acc.x += __shfl_xor_sync(0xffffffffu, acc.x, 8);
        acc.y += __shfl_xor_sync(0xffffffffu, acc.y, 8);
        acc.z += __shfl_xor_sync(0xffffffffu, acc.z, 8);
        acc.w += __shfl_xor_sync(0xffffffffu, acc.w, 8);
        acc.x += __shfl_xor_sync(0xffffffffu, acc.x, 16);
        acc.y += __shfl_xor_sync(0xffffffffu, acc.y, 16);
        acc.z += __shfl_xor_sync(0xffffffffu, acc.z, 16);
        acc.w += __shfl_xor_sync(0xffffffffu, acc.w, 16);

        const float inv = 1.f / psum;
        if (g == 0) {
            float4 o;
            o.x = fmaxf(acc.x * inv, 0.f);
            o.y = fmaxf(acc.y * inv, 0.f);
            o.z = fmaxf(acc.z * inv, 0.f);
            o.w = fmaxf(acc.w * inv, 0.f);
            *(float4*)(out + ((size_t)(b * N_ + n)) * OUT_DIM + h * D_ + 4 * s) = o;
        }
    }
}

// ======================= launch =======================
extern "C" void kernel_launch(void* const* d_in, const int* in_sizes, int n_in,
                              void* d_out, int out_size) {
    const float* A   = (const float*)d_in[0];
    const float* X   = (const float*)d_in[1];
    const float* W   = (const float*)d_in[2];
    const float* fc1 = (const float*)d_in[3];
    const float* fc2 = (const float*)d_in[4];
    float* out = (float*)d_out;

    const size_t smem4 = (size_t)N_ * D_ * 2 + (size_t)N_ * sizeof(float);   // 69632 B
    cudaFuncSetAttribute(k_attn, cudaFuncAttributeMaxDynamicSharedMemorySize, (int)smem4);

    k_fused<<<128 + ROWS_ / 8, 256>>>(X, W, A);
    k_scores<<<(ROWS_ * H_) / 256, 256>>>(fc1, fc2);
    k_attn<<<dim3(RB, H_, B_), 384, smem4>>>(out);
}

// round 10
// speedup vs baseline: 1.2912x; 1.2912x over previous
#include <cuda_runtime.h>
#include <cuda_fp16.h>

// Problem dims (fixed)
#define B_      8
#define N_      1024
#define IN_DIM  256
#define OUT_DIM 256
#define H_      8
#define D_      32
#define ROWS_   (B_ * N_)          // 8192

// ---------------- static device scratch (no allocations allowed) ----------------
__device__ float           g_inputs[(size_t)ROWS_ * OUT_DIM];   // 32MB: X@W, [row][h*32+d]
__device__ __half          g_vhalf[(size_t)B_ * H_ * N_ * D_];  // 16MB: fp16 V, head-major
__device__ float           g_self[B_ * H_ * N_];                // [b][h][n]
__device__ float           g_neigh[B_ * H_ * N_];               // [b][h][n]
__device__ unsigned short  g_idx[(size_t)ROWS_ * N_];           // 16MB CSR cols (fixed stride)
__device__ int             g_cnt[ROWS_];

// ======================= K1: SGEMM inputs = X @ W =======================
// M=8192, N=256, K=256.  128x64 tiles -> 256 CTAs (one full wave at 2 CTA/SM),
// 256 threads, 8x4 microtile, double-buffered smem (1 sync per K-tile).
#define BM 128
#define BN 64
#define BK 16
#define NKT (IN_DIM / BK)   // 16

__global__ __launch_bounds__(256) void k_gemm(const float* __restrict__ X,
                                              const float* __restrict__ W) {
    __shared__ float As[2][BK][BM];   // transposed A tile
    __shared__ float Bs[2][BK][BN];

    const int tid  = threadIdx.x;
    const int row0 = (blockIdx.x >> 2) * BM;
    const int col0 = (blockIdx.x & 3) * BN;
    const int tr   = (tid >> 4) * 8;   // 0..120
    const int tc   = (tid & 15) * 4;   // 0..60

    // A-tile load mapping: 512 float4 (128 rows x 4 float4), 2 per thread
    const int ar0 = (tid * 2) >> 2;          // row of first float4
    const int ac0 = ((tid * 2) & 3) * 4;     // k-offset of first float4
    const int ar1 = (tid * 2 + 1) >> 2;
    const int ac1 = ((tid * 2 + 1) & 3) * 4;
    // B-tile load mapping: 256 float4 (16 rows x 16 float4), 1 per thread
    const int br = tid >> 4;
    const int bc = (tid & 15) * 4;

    float acc[8][4];
#pragma unroll
    for (int i = 0; i < 8; i++)
#pragma unroll
        for (int j = 0; j < 4; j++) acc[i][j] = 0.f;

    // prefetch tile 0
    float4 pa0 = *(const float4*)(X + (size_t)(row0 + ar0) * IN_DIM + ac0);
    float4 pa1 = *(const float4*)(X + (size_t)(row0 + ar1) * IN_DIM + ac1);
    float4 pb  = *(const float4*)(W + (size_t)br * OUT_DIM + col0 + bc);

    int buf = 0;
    // store tile 0
    As[0][ac0 + 0][ar0] = pa0.x; As[0][ac0 + 1][ar0] = pa0.y;
    As[0][ac0 + 2][ar0] = pa0.z; As[0][ac0 + 3][ar0] = pa0.w;
    As[0][ac1 + 0][ar1] = pa1.x; As[0][ac1 + 1][ar1] = pa1.y;
    As[0][ac1 + 2][ar1] = pa1.z; As[0][ac1 + 3][ar1] = pa1.w;
    *(float4*)&Bs[0][br][bc] = pb;
    __syncthreads();

    for (int kt = 0; kt < NKT; kt++) {
        const bool more = (kt + 1 < NKT);
        if (more) {
            const int k0 = (kt + 1) * BK;
            pa0 = *(const float4*)(X + (size_t)(row0 + ar0) * IN_DIM + k0 + ac0);
            pa1 = *(const float4*)(X + (size_t)(row0 + ar1) * IN_DIM + k0 + ac1);
            pb  = *(const float4*)(W + (size_t)(k0 + br) * OUT_DIM + col0 + bc);
        }

#pragma unroll
        for (int k = 0; k < BK; k++) {
            float a[8], b[4];
            *(float4*)&a[0] = *(const float4*)&As[buf][k][tr];
            *(float4*)&a[4] = *(const float4*)&As[buf][k][tr + 4];
            *(float4*)&b[0] = *(const float4*)&Bs[buf][k][tc];
#pragma unroll
            for (int i = 0; i < 8; i++)
#pragma unroll
                for (int j = 0; j < 4; j++) acc[i][j] = fmaf(a[i], b[j], acc[i][j]);
        }

        if (more) {
            const int nb = buf ^ 1;
            As[nb][ac0 + 0][ar0] = pa0.x; As[nb][ac0 + 1][ar0] = pa0.y;
            As[nb][ac0 + 2][ar0] = pa0.z; As[nb][ac0 + 3][ar0] = pa0.w;
            As[nb][ac1 + 0][ar1] = pa1.x; As[nb][ac1 + 1][ar1] = pa1.y;
            As[nb][ac1 + 2][ar1] = pa1.z; As[nb][ac1 + 3][ar1] = pa1.w;
            *(float4*)&Bs[nb][br][bc] = pb;
            __syncthreads();
            buf = nb;
        }
    }

#pragma unroll
    for (int i = 0; i < 8; i++) {
        float4 v0 = {acc[i][0], acc[i][1], acc[i][2], acc[i][3]};
        *(float4*)(g_inputs + (size_t)(row0 + tr + i) * OUT_DIM + col0 + tc) = v0;
    }
}

// ======================= K2: adjacency -> CSR (ballot compaction) =======================
__global__ __launch_bounds__(256) void k_csr(const float* __restrict__ A) {
    int warp = threadIdx.x >> 5;
    int lane = threadIdx.x & 31;
    int row  = blockIdx.x * 8 + warp;

    const float* Arow = A + (size_t)row * N_;
    unsigned short* out = g_idx + (size_t)row * N_;

    int base = 0;
#pragma unroll
    for (int it = 0; it < 8; it++) {
        float4 v = *(const float4*)(Arow + it * 128 + lane * 4);
        float vals[4] = {v.x, v.y, v.z, v.w};
#pragma unroll
        for (int e = 0; e < 4; e++) {
            bool nz = (vals[e] != 0.f);
            unsigned mask = __ballot_sync(0xffffffffu, nz);
            if (nz) {
                int pos = base + __popc(mask & ((1u << lane) - 1u));
                out[pos] = (unsigned short)(it * 128 + lane * 4 + e);
            }
            base += __popc(mask);
        }
    }
    if (lane == 0) g_cnt[row] = base;
}

// ======================= K3: attention scores + fp16 V pre-convert =======================
// gid -> (h = gid>>13, row = gid&8191): warps write contiguous per-head planes.
__global__ __launch_bounds__(256) void k_scores(const float* __restrict__ fc1,
                                                const float* __restrict__ fc2) {
    __shared__ float f1[H_ * D_];
    __shared__ float f2[H_ * D_];
    int t = threadIdx.x;
    f1[t] = fc1[t];
    f2[t] = fc2[t];
    __syncthreads();

    int gid = blockIdx.x * 256 + t;
    int h   = gid >> 13;
    int row = gid & (ROWS_ - 1);
    int b_  = row >> 10;
    int n   = row & (N_ - 1);

    const float* ip = g_inputs + (size_t)row * OUT_DIM + h * D_;
    __half* vdst = g_vhalf + ((size_t)(b_ * H_ + h) * N_ + n) * D_;

    float s1 = 0.f, s2 = 0.f;
#pragma unroll
    for (int i = 0; i < D_; i += 4) {
        float4 v = *(const float4*)(ip + i);
        float4 a = *(const float4*)(f1 + h * D_ + i);
        float4 bq = *(const float4*)(f2 + h * D_ + i);
        s1 += v.x * a.x + v.y * a.y + v.z * a.z + v.w * a.w;
        s2 += v.x * bq.x + v.y * bq.y + v.z * bq.z + v.w * bq.w;
        __half2 h01 = __floats2half2_rn(v.x, v.y);
        __half2 h23 = __floats2half2_rn(v.z, v.w);
        uint2 pk;
        pk.x = *(unsigned*)&h01;
        pk.y = *(unsigned*)&h23;
        *(uint2*)(vdst + i) = pk;
    }
    g_self [(b_ * H_ + h) * N_ + n] = s1;
    g_neigh[(b_ * H_ + h) * N_ + n] = s2;
}

// ======================= K4: sparse softmax-attention aggregation =======================
// fp16 V tile (64KB, pure copy from g_vhalf) + fp32 neigh scores (4KB) = 68KB smem.
// 384 threads, 3 CTAs/SM -> 36 resident warps. Lane layout: g=lane>>3 picks 1-of-4
// edges per step, s=lane&7 -> dims [4s,4s+4). (p,m) travel in ONE shfl word.
#define RB 8   // row-blocks per (b,h) -> 128 rows per CTA, grid = 512 CTAs

__global__ __launch_bounds__(384, 3) void k_attn(float* __restrict__ out) {
    extern __shared__ char smraw[];
    __half* Vs = (__half*)smraw;                       // [1024][32] fp16
    float*  ns = (float*)(smraw + N_ * D_ * 2);        // [1024]

    const int b  = blockIdx.z;
    const int h  = blockIdx.y;
    const int rb = blockIdx.x;
    const int tid = threadIdx.x;

    // stage V (pure 64KB copy) + neigh scores
    {
        const uint4* vsrc = (const uint4*)(g_vhalf + (size_t)(b * H_ + h) * N_ * D_);
        uint4* vdst = (uint4*)Vs;
        for (int f = tid; f < N_ * D_ / 8; f += 384) vdst[f] = vsrc[f];
        const float* nsrc = g_neigh + (b * H_ + h) * N_;
        for (int m = tid; m < N_; m += 384) ns[m] = nsrc[m];
    }
    __syncthreads();

    const int warp = tid >> 5;
    const int lane = tid & 31;
    const int g    = lane >> 3;
    const int s    = lane & 7;
    const int rbase = rb * (N_ / RB);

    for (int n = rbase + warp; n < rbase + N_ / RB; n += 12) {
        const int row = b * N_ + n;
        const int nb  = g_cnt[row];
        const float self = g_self[(b * H_ + h) * N_ + n];
        const unsigned short* ip = g_idx + (size_t)row * N_;

        // ---- front: slots 2*lane, 2*lane+1 via one ushort2 load
        const ushort2 mm = *(const ushort2*)(ip + 2 * lane);
        const unsigned m0 = mm.x, m1 = mm.y;
        const bool a0 = (2 * lane < nb);
        const bool a1 = (2 * lane + 1 < nb);
        float p0 = 0.f, p1 = 0.f;
        if (a0) {
            float sc = self + ns[m0];
            sc = (sc >= 0.f) ? sc : 0.01f * sc;
            p0 = __expf(sc);
        }
        if (a1) {
            float sc = self + ns[m1];
            sc = (sc >= 0.f) ? sc : 0.01f * sc;
            p1 = __expf(sc);
        }
        float psum = p0 + p1;
        const unsigned pm0 = a0 ? ((__float_as_uint(p0) & ~1023u) | m0) : 0u;
        const unsigned pm1 = a1 ? ((__float_as_uint(p1) & ~1023u) | m1) : 0u;
        float4 acc = {0.f, 0.f, 0.f, 0.f};

        // ---- rare tail: nb > 64
        for (int base = 64; base < nb; base += 32) {
            unsigned mt = 0;
            float pt = 0.f;
            if (base + lane < nb) {
                mt = ip[base + lane];
                float sc = self + ns[mt];
                sc = (sc >= 0.f) ? sc : 0.01f * sc;
                pt = __expf(sc);
            }
            psum += pt;
            unsigned pmt = (__float_as_uint(pt) & ~1023u) | mt;
#pragma unroll
            for (int t = 0; t < 8; t++) {
                unsigned pmj = __shfl_sync(0xffffffffu, pmt, 4 * t + g);
                float    pj  = __uint_as_float(pmj);
                unsigned mj  = pmj & 1023u;
                uint2 hv = *(const uint2*)(Vs + (mj << 5) + (s << 2));
                float2 f01 = __half22float2(*(__half2*)&hv.x);
                float2 f23 = __half22float2(*(__half2*)&hv.y);
                acc.x = fmaf(pj, f01.x, acc.x);
                acc.y = fmaf(pj, f01.y, acc.y);
                acc.z = fmaf(pj, f23.x, acc.z);
                acc.w = fmaf(pj, f23.y, acc.w);
            }
        }

        // ---- main body: 16 fully-unrolled independent steps, one shfl each
#pragma unroll
        for (int t = 0; t < 8; t++) {
            unsigned pmj = __shfl_sync(0xffffffffu, pm0, 4 * t + g);
            float    pj  = __uint_as_float(pmj);
            unsigned mj  = pmj & 1023u;
            uint2 hv = *(const uint2*)(Vs + (mj << 5) + (s << 2));
            float2 f01 = __half22float2(*(__half2*)&hv.x);
            float2 f23 = __half22float2(*(__half2*)&hv.y);
            acc.x = fmaf(pj, f01.x, acc.x);
            acc.y = fmaf(pj, f01.y, acc.y);
            acc.z = fmaf(pj, f23.x, acc.z);
            acc.w = fmaf(pj, f23.y, acc.w);
        }
#pragma unroll
        for (int t = 0; t < 8; t++) {
            unsigned pmj = __shfl_sync(0xffffffffu, pm1, 4 * t + g);
            float    pj  = __uint_as_float(pmj);
            unsigned mj  = pmj & 1023u;
            uint2 hv = *(const uint2*)(Vs + (mj << 5) + (s << 2));
            float2 f01 = __half22float2(*(__half2*)&hv.x);
            float2 f23 = __half22float2(*(__half2*)&hv.y);
            acc.x = fmaf(pj, f01.x, acc.x);
            acc.y = fmaf(pj, f01.y, acc.y);
            acc.z = fmaf(pj, f23.x, acc.z);
            acc.w = fmaf(pj, f23.y, acc.w);
        }

        // reduce denominator over all 32 lanes
#pragma unroll
        for (int off = 16; off; off >>= 1) psum += __shfl_xor_sync(0xffffffffu, psum, off);
        // reduce acc across the 4 edge-groups (lane bits 3..4)
        acc.x += __shfl_xor_sync(0xffffffffu, acc.x, 8);
        acc.y += __shfl_xor_sync(0xffffffffu, acc.y, 8);
        acc.z += __shfl_xor_sync(0xffffffffu, acc.z, 8);
        acc.w += __shfl_xor_sync(0xffffffffu, acc.w, 8);
        acc.x += __shfl_xor_sync(0xffffffffu, acc.x, 16);
        acc.y += __shfl_xor_sync(0xffffffffu, acc.y, 16);
        acc.z += __shfl_xor_sync(0xffffffffu, acc.z, 16);
        acc.w += __shfl_xor_sync(0xffffffffu, acc.w, 16);

        const float inv = 1.f / psum;
        if (g == 0) {
            float4 o;
            o.x = fmaxf(acc.x * inv, 0.f);
            o.y = fmaxf(acc.y * inv, 0.f);
            o.z = fmaxf(acc.z * inv, 0.f);
            o.w = fmaxf(acc.w * inv, 0.f);
            *(float4*)(out + ((size_t)(b * N_ + n)) * OUT_DIM + h * D_ + 4 * s) = o;
        }
    }
}

// ======================= launch =======================
extern "C" void kernel_launch(void* const* d_in, const int* in_sizes, int n_in,
                              void* d_out, int out_size) {
    const float* A   = (const float*)d_in[0];
    const float* X   = (const float*)d_in[1];
    const float* W   = (const float*)d_in[2];
    const float* fc1 = (const float*)d_in[3];
    const float* fc2 = (const float*)d_in[4];
    float* out = (float*)d_out;

    const size_t smem4 = (size_t)N_ * D_ * 2 + (size_t)N_ * sizeof(float);   // 69632 B
    cudaFuncSetAttribute(k_attn, cudaFuncAttributeMaxDynamicSharedMemorySize, (int)smem4);

    k_gemm<<<(ROWS_ / BM) * (OUT_DIM / BN), 256>>>(X, W);   // 256 CTAs
    k_csr<<<ROWS_ / 8, 256>>>(A);
    k_scores<<<(ROWS_ * H_) / 256, 256>>>(fc1, fc2);
    k_attn<<<dim3(RB, H_, B_), 384, smem4>>>(out);
}

// round 11
// speedup vs baseline: 1.4279x; 1.1059x over previous
#include <cuda_runtime.h>
#include <cuda_fp16.h>

// Problem dims (fixed)
#define B_      8
#define N_      1024
#define IN_DIM  256
#define OUT_DIM 256
#define H_      8
#define D_      32
#define ROWS_   (B_ * N_)          // 8192

// ---------------- static device scratch (no allocations allowed) ----------------
__device__ __half          g_vhalf[(size_t)B_ * H_ * N_ * D_];  // 4MB: fp16 V, head-major
__device__ float           g_self[B_ * H_ * N_];                // [b][h][n]
__device__ float           g_neigh[B_ * H_ * N_];               // [b][h][n]
__device__ unsigned short  g_idx[(size_t)ROWS_ * N_];           // 16MB CSR cols (fixed stride)
__device__ int             g_cnt[ROWS_];

// ======================= K1: SGEMM (X@W) + fused scores/V epilogue =======================
// M=8192, N=256, K=256.  128x64 tiles -> 256 CTAs, 256 threads, 8x4 microtile,
// double-buffered smem. Each CTA's 64-col tile = exactly 2 heads, so the epilogue
// computes s1/s2 = <inputs[row,h,:], fc1/fc2[h]> via 8-lane shfl reductions and
// writes fp16 V directly — g_inputs never exists, k_scores is gone.
#define BM 128
#define BN 64
#define BK 16
#define NKT (IN_DIM / BK)   // 16

__global__ __launch_bounds__(256, 2) void k_gemm(const float* __restrict__ X,
                                                 const float* __restrict__ W,
                                                 const float* __restrict__ fc1,
                                                 const float* __restrict__ fc2) {
    __shared__ float As[2][BK][BM];   // transposed A tile
    __shared__ float Bs[2][BK][BN];

    const int tid  = threadIdx.x;
    const int row0 = (blockIdx.x >> 2) * BM;
    const int col0 = (blockIdx.x & 3) * BN;
    const int tr   = (tid >> 4) * 8;   // 0..120
    const int tc   = (tid & 15) * 4;   // 0..60

    // A-tile load mapping: 512 float4 (128 rows x 4 float4), 2 per thread
    const int ar0 = (tid * 2) >> 2;
    const int ac0 = ((tid * 2) & 3) * 4;
    const int ar1 = (tid * 2 + 1) >> 2;
    const int ac1 = ((tid * 2 + 1) & 3) * 4;
    // B-tile load mapping: 256 float4 (16 rows x 16 float4), 1 per thread
    const int br = tid >> 4;
    const int bc = (tid & 15) * 4;

    float acc[8][4];
#pragma unroll
    for (int i = 0; i < 8; i++)
#pragma unroll
        for (int j = 0; j < 4; j++) acc[i][j] = 0.f;

    // prefetch tile 0
    float4 pa0 = *(const float4*)(X + (size_t)(row0 + ar0) * IN_DIM + ac0);
    float4 pa1 = *(const float4*)(X + (size_t)(row0 + ar1) * IN_DIM + ac1);
    float4 pb  = *(const float4*)(W + (size_t)br * OUT_DIM + col0 + bc);

    int buf = 0;
    As[0][ac0 + 0][ar0] = pa0.x; As[0][ac0 + 1][ar0] = pa0.y;
    As[0][ac0 + 2][ar0] = pa0.z; As[0][ac0 + 3][ar0] = pa0.w;
    As[0][ac1 + 0][ar1] = pa1.x; As[0][ac1 + 1][ar1] = pa1.y;
    As[0][ac1 + 2][ar1] = pa1.z; As[0][ac1 + 3][ar1] = pa1.w;
    *(float4*)&Bs[0][br][bc] = pb;
    __syncthreads();

    for (int kt = 0; kt < NKT; kt++) {
        const bool more = (kt + 1 < NKT);
        if (more) {
            const int k0 = (kt + 1) * BK;
            pa0 = *(const float4*)(X + (size_t)(row0 + ar0) * IN_DIM + k0 + ac0);
            pa1 = *(const float4*)(X + (size_t)(row0 + ar1) * IN_DIM + k0 + ac1);
            pb  = *(const float4*)(W + (size_t)(k0 + br) * OUT_DIM + col0 + bc);
        }

#pragma unroll
        for (int k = 0; k < BK; k++) {
            float a[8], b[4];
            *(float4*)&a[0] = *(const float4*)&As[buf][k][tr];
            *(float4*)&a[4] = *(const float4*)&As[buf][k][tr + 4];
            *(float4*)&b[0] = *(const float4*)&Bs[buf][k][tc];
#pragma unroll
            for (int i = 0; i < 8; i++)
#pragma unroll
                for (int j = 0; j < 4; j++) acc[i][j] = fmaf(a[i], b[j], acc[i][j]);
        }

        if (more) {
            const int nb = buf ^ 1;
            As[nb][ac0 + 0][ar0] = pa0.x; As[nb][ac0 + 1][ar0] = pa0.y;
            As[nb][ac0 + 2][ar0] = pa0.z; As[nb][ac0 + 3][ar0] = pa0.w;
            As[nb][ac1 + 0][ar1] = pa1.x; As[nb][ac1 + 1][ar1] = pa1.y;
            As[nb][ac1 + 2][ar1] = pa1.z; As[nb][ac1 + 3][ar1] = pa1.w;
            *(float4*)&Bs[nb][br][bc] = pb;
            __syncthreads();
            buf = nb;
        }
    }

    // ---------------- epilogue: scores + fp16 V ----------------
    const int lane = tid & 31;
    const int head_local = (tid >> 3) & 1;        // which of the tile's 2 heads
    const int h  = (col0 >> 5) + head_local;
    const int hc = tc & 31;                       // dim offset within head (0..28)
    const int b  = row0 >> 10;                    // BM=128 divides N_: one batch per CTA

    const float4 f1v = *(const float4*)(fc1 + h * D_ + hc);
    const float4 f2v = *(const float4*)(fc2 + h * D_ + hc);

#pragma unroll
    for (int i = 0; i < 8; i++) {
        const int row = row0 + tr + i;
        const int n   = row & (N_ - 1);

        float s1 = acc[i][0] * f1v.x + acc[i][1] * f1v.y + acc[i][2] * f1v.z + acc[i][3] * f1v.w;
        float s2 = acc[i][0] * f2v.x + acc[i][1] * f2v.y + acc[i][2] * f2v.z + acc[i][3] * f2v.w;
        // 8-lane groups (same row, same head): offsets 1,2,4 stay in-group
        s1 += __shfl_xor_sync(0xffffffffu, s1, 1);
        s2 += __shfl_xor_sync(0xffffffffu, s2, 1);
        s1 += __shfl_xor_sync(0xffffffffu, s1, 2);
        s2 += __shfl_xor_sync(0xffffffffu, s2, 2);
        s1 += __shfl_xor_sync(0xffffffffu, s1, 4);
        s2 += __shfl_xor_sync(0xffffffffu, s2, 4);
        if ((lane & 7) == 0) {
            g_self [(b * H_ + h) * N_ + n] = s1;
            g_neigh[(b * H_ + h) * N_ + n] = s2;
        }

        __half2 h01 = __floats2half2_rn(acc[i][0], acc[i][1]);
        __half2 h23 = __floats2half2_rn(acc[i][2], acc[i][3]);
        uint2 pk;
        pk.x = *(unsigned*)&h01;
        pk.y = *(unsigned*)&h23;
        *(uint2*)(g_vhalf + ((size_t)(b * H_ + h) * N_ + n) * D_ + hc) = pk;
    }
}

// ======================= K2: adjacency -> CSR (ballot compaction) =======================
__global__ __launch_bounds__(256) void k_csr(const float* __restrict__ A) {
    int warp = threadIdx.x >> 5;
    int lane = threadIdx.x & 31;
    int row  = blockIdx.x * 8 + warp;

    const float* Arow = A + (size_t)row * N_;
    unsigned short* out = g_idx + (size_t)row * N_;

    int base = 0;
#pragma unroll
    for (int it = 0; it < 8; it++) {
        float4 v = *(const float4*)(Arow + it * 128 + lane * 4);
        float vals[4] = {v.x, v.y, v.z, v.w};
#pragma unroll
        for (int e = 0; e < 4; e++) {
            bool nz = (vals[e] != 0.f);
            unsigned mask = __ballot_sync(0xffffffffu, nz);
            if (nz) {
                int pos = base + __popc(mask & ((1u << lane) - 1u));
                out[pos] = (unsigned short)(it * 128 + lane * 4 + e);
            }
            base += __popc(mask);
        }
    }
    if (lane == 0) g_cnt[row] = base;
}

// ======================= K3: sparse softmax-attention aggregation =======================
// fp16 V tile (64KB, pure copy from g_vhalf) + fp32 neigh scores (4KB) = 68KB smem.
// 384 threads, 3 CTAs/SM -> 36 resident warps. Lane layout: g=lane>>3 picks 1-of-4
// edges per step, s=lane&7 -> dims [4s,4s+4). (p,m) travel in ONE shfl word.
#define RB 8   // row-blocks per (b,h) -> 128 rows per CTA, grid = 512 CTAs

__global__ __launch_bounds__(384, 3) void k_attn(float* __restrict__ out) {
    extern __shared__ char smraw[];
    __half* Vs = (__half*)smraw;                       // [1024][32] fp16
    float*  ns = (float*)(smraw + N_ * D_ * 2);        // [1024]

    const int b  = blockIdx.z;
    const int h  = blockIdx.y;
    const int rb = blockIdx.x;
    const int tid = threadIdx.x;

    // stage V (pure 64KB copy) + neigh scores
    {
        const uint4* vsrc = (const uint4*)(g_vhalf + (size_t)(b * H_ + h) * N_ * D_);
        uint4* vdst = (uint4*)Vs;
        for (int f = tid; f < N_ * D_ / 8; f += 384) vdst[f] = vsrc[f];
        const float* nsrc = g_neigh + (b * H_ + h) * N_;
        for (int m = tid; m < N_; m += 384) ns[m] = nsrc[m];
    }
    __syncthreads();

    const int warp = tid >> 5;
    const int lane = tid & 31;
    const int g    = lane >> 3;
    const int s    = lane & 7;
    const int rbase = rb * (N_ / RB);

    for (int n = rbase + warp; n < rbase + N_ / RB; n += 12) {
        const int row = b * N_ + n;
        const int nb  = g_cnt[row];
        const float self = g_self[(b * H_ + h) * N_ + n];
        const unsigned short* ip = g_idx + (size_t)row * N_;

        // ---- front: slots 2*lane, 2*lane+1 via one ushort2 load
        const ushort2 mm = *(const ushort2*)(ip + 2 * lane);
        const unsigned m0 = mm.x, m1 = mm.y;
        const bool a0 = (2 * lane < nb);
        const bool a1 = (2 * lane + 1 < nb);
        float p0 = 0.f, p1 = 0.f;
        if (a0) {
            float sc = self + ns[m0];
            sc = (sc >= 0.f) ? sc : 0.01f * sc;
            p0 = __expf(sc);
        }
        if (a1) {
            float sc = self + ns[m1];
            sc = (sc >= 0.f) ? sc : 0.01f * sc;
            p1 = __expf(sc);
        }
        float psum = p0 + p1;
        const unsigned pm0 = a0 ? ((__float_as_uint(p0) & ~1023u) | m0) : 0u;
        const unsigned pm1 = a1 ? ((__float_as_uint(p1) & ~1023u) | m1) : 0u;
        float4 acc = {0.f, 0.f, 0.f, 0.f};

        // ---- rare tail: nb > 64
        for (int base = 64; base < nb; base += 32) {
            unsigned mt = 0;
            float pt = 0.f;
            if (base + lane < nb) {
                mt = ip[base + lane];
                float sc = self + ns[mt];
                sc = (sc >= 0.f) ? sc : 0.01f * sc;
                pt = __expf(sc);
            }
            psum += pt;
            unsigned pmt = (__float_as_uint(pt) & ~1023u) | mt;
#pragma unroll
            for (int t = 0; t < 8; t++) {
                unsigned pmj = __shfl_sync(0xffffffffu, pmt, 4 * t + g);
                float    pj  = __uint_as_float(pmj);
                unsigned mj  = pmj & 1023u;
                uint2 hv = *(const uint2*)(Vs + (mj << 5) + (s << 2));
                float2 f01 = __half22float2(*(__half2*)&hv.x);
                float2 f23 = __half22float2(*(__half2*)&hv.y);
                acc.x = fmaf(pj, f01.x, acc.x);
                acc.y = fmaf(pj, f01.y, acc.y);
                acc.z = fmaf(pj, f23.x, acc.z);
                acc.w = fmaf(pj, f23.y, acc.w);
            }
        }

        // ---- main body: 16 fully-unrolled independent steps, one shfl each
#pragma unroll
        for (int t = 0; t < 8; t++) {
            unsigned pmj = __shfl_sync(0xffffffffu, pm0, 4 * t + g);
            float    pj  = __uint_as_float(pmj);
            unsigned mj  = pmj & 1023u;
            uint2 hv = *(const uint2*)(Vs + (mj << 5) + (s << 2));
            float2 f01 = __half22float2(*(__half2*)&hv.x);
            float2 f23 = __half22float2(*(__half2*)&hv.y);
            acc.x = fmaf(pj, f01.x, acc.x);
            acc.y = fmaf(pj, f01.y, acc.y);
            acc.z = fmaf(pj, f23.x, acc.z);
            acc.w = fmaf(pj, f23.y, acc.w);
        }
#pragma unroll
        for (int t = 0; t < 8; t++) {
            unsigned pmj = __shfl_sync(0xffffffffu, pm1, 4 * t + g);
            float    pj  = __uint_as_float(pmj);
            unsigned mj  = pmj & 1023u;
            uint2 hv = *(const uint2*)(Vs + (mj << 5) + (s << 2));
            float2 f01 = __half22float2(*(__half2*)&hv.x);
            float2 f23 = __half22float2(*(__half2*)&hv.y);
            acc.x = fmaf(pj, f01.x, acc.x);
            acc.y = fmaf(pj, f01.y, acc.y);
            acc.z = fmaf(pj, f23.x, acc.z);
            acc.w = fmaf(pj, f23.y, acc.w);
        }

        // reduce denominator over all 32 lanes
#pragma unroll
        for (int off = 16; off; off >>= 1) psum += __shfl_xor_sync(0xffffffffu, psum, off);
        // reduce acc across the 4 edge-groups (lane bits 3..4)
        acc.x += __shfl_xor_sync(0xffffffffu, acc.x, 8);
        acc.y += __shfl_xor_sync(0xffffffffu, acc.y, 8);
        acc.z += __shfl_xor_sync(0xffffffffu, acc.z, 8);
        acc.w += __shfl_xor_sync(0xffffffffu, acc.w, 8);
        acc.x += __shfl_xor_sync(0xffffffffu, acc.x, 16);
        acc.y += __shfl_xor_sync(0xffffffffu, acc.y, 16);
        acc.z += __shfl_xor_sync(0xffffffffu, acc.z, 16);
        acc.w += __shfl_xor_sync(0xffffffffu, acc.w, 16);

        const float inv = 1.f / psum;
        if (g == 0) {
            float4 o;
            o.x = fmaxf(acc.x * inv, 0.f);
            o.y = fmaxf(acc.y * inv, 0.f);
            o.z = fmaxf(acc.z * inv, 0.f);
            o.w = fmaxf(acc.w * inv, 0.f);
            *(float4*)(out + ((size_t)(b * N_ + n)) * OUT_DIM + h * D_ + 4 * s) = o;
        }
    }
}

// ======================= launch =======================
extern "C" void kernel_launch(void* const* d_in, const int* in_sizes, int n_in,
                              void* d_out, int out_size) {
    const float* A   = (const float*)d_in[0];
    const float* X   = (const float*)d_in[1];
    const float* W   = (const float*)d_in[2];
    const float* fc1 = (const float*)d_in[3];
    const float* fc2 = (const float*)d_in[4];
    float* out = (float*)d_out;

    const size_t smem4 = (size_t)N_ * D_ * 2 + (size_t)N_ * sizeof(float);   // 69632 B
    cudaFuncSetAttribute(k_attn, cudaFuncAttributeMaxDynamicSharedMemorySize, (int)smem4);

    k_gemm<<<(ROWS_ / BM) * (OUT_DIM / BN), 256>>>(X, W, fc1, fc2);   // 256 CTAs
    k_csr<<<ROWS_ / 8, 256>>>(A);
    k_attn<<<dim3(RB, H_, B_), 384, smem4>>>(out);
}

// round 12
// speedup vs baseline: 1.5748x; 1.1028x over previous
#include <cuda_runtime.h>
#include <cuda_fp16.h>
#include <cuda_bf16.h>

// Problem dims (fixed)
#define B_      8
#define N_      1024
#define IN_DIM  256
#define OUT_DIM 256
#define H_      8
#define D_      32
#define ROWS_   (B_ * N_)          // 8192

// ---------------- static device scratch (no allocations allowed) ----------------
__device__ __half          g_vhalf[(size_t)B_ * H_ * N_ * D_];  // 4MB: fp16 V, head-major
__device__ float           g_self[B_ * H_ * N_];                // [b][h][n]
__device__ float           g_neigh[B_ * H_ * N_];               // [b][h][n]
__device__ unsigned short  g_idx[(size_t)ROWS_ * N_];           // 16MB CSR cols (fixed stride)
__device__ int             g_cnt[ROWS_];

// ======================= K1: split-bf16 tensor-core GEMM + scores/V epilogue ==========
// inputs = X@W via 3x bf16 mma (hi*hi + hi*lo + lo*hi), fp32 accum: ~1.5e-5 rel err.
// CTA 128x64 (256 CTAs, full wave), 8 warps, warp tile 32x32 (one head per warp).
// smem: hi/lo tiles, K=32 double-buffered, pitch 40 halves (80B) -> conflict-free frags.
#define BM 128
#define BN 64
#define BKK 32
#define NKI (IN_DIM / BKK)   // 8
#define PITCH 40
#define BUFH  15360          // halves per buffer: (128+128+64+64)*40
#define AS_LO_OFF 5120
#define BS_OFF    10240
#define BS_LO_OFF 2560

__device__ __forceinline__ void mma16816(float* c, const unsigned* a, const unsigned* b) {
    asm volatile(
        "mma.sync.aligned.m16n8k16.row.col.f32.bf16.bf16.f32 "
        "{%0,%1,%2,%3}, {%4,%5,%6,%7}, {%8,%9}, {%0,%1,%2,%3};\n"
        : "+f"(c[0]), "+f"(c[1]), "+f"(c[2]), "+f"(c[3])
        : "r"(a[0]), "r"(a[1]), "r"(a[2]), "r"(a[3]), "r"(b[0]), "r"(b[1]));
}

__global__ __launch_bounds__(256, 2) void k_gemm(const float* __restrict__ X,
                                                 const float* __restrict__ W,
                                                 const float* __restrict__ fc1,
                                                 const float* __restrict__ fc2) {
    extern __shared__ __nv_bfloat16 smb[];

    const int tid  = threadIdx.x;
    const int row0 = (blockIdx.x >> 2) * BM;
    const int col0 = (blockIdx.x & 3) * BN;
    const int warp = tid >> 5;
    const int lane = tid & 31;
    const int wm   = warp >> 1;          // 0..3  (32-row warp tile)
    const int wn   = warp & 1;           // 0..1  (32-col warp tile = 1 head)
    const int gid  = lane >> 2;          // 0..7
    const int tig  = lane & 3;           // 0..3

    float c[2][4][4];
#pragma unroll
    for (int mt = 0; mt < 2; mt++)
#pragma unroll
        for (int nt = 0; nt < 4; nt++)
#pragma unroll
            for (int q = 0; q < 4; q++) c[mt][nt][q] = 0.f;

    // prefetch registers
    float4 pa[4], pw[2];
    // A strip mapping: f = tid + l*256 (0..1023): row = f>>3, c4 = (f&7)*4
    // W strip mapping: f = tid + l*256 (0..511):  kr  = f>>4, c4 = (f&15)*4

    auto prefetch = [&](int k0) {
#pragma unroll
        for (int l = 0; l < 4; l++) {
            int f = tid + l * 256;
            pa[l] = *(const float4*)(X + (size_t)(row0 + (f >> 3)) * IN_DIM + k0 + (f & 7) * 4);
        }
#pragma unroll
        for (int l = 0; l < 2; l++) {
            int f = tid + l * 256;
            pw[l] = *(const float4*)(W + (size_t)(k0 + (f >> 4)) * OUT_DIM + col0 + (f & 15) * 4);
        }
    };

    auto stage = [&](int nb) {
        const int boff = nb * BUFH;
#pragma unroll
        for (int l = 0; l < 4; l++) {
            int f = tid + l * 256;
            int tgt = boff + (f >> 3) * PITCH + (f & 7) * 4;
            float4 v = pa[l];
            __nv_bfloat162 hp0 = __floats2bfloat162_rn(v.x, v.y);
            __nv_bfloat162 hp1 = __floats2bfloat162_rn(v.z, v.w);
            __nv_bfloat162 lp0 = __floats2bfloat162_rn(v.x - __bfloat162float(hp0.x),
                                                       v.y - __bfloat162float(hp0.y));
            __nv_bfloat162 lp1 = __floats2bfloat162_rn(v.z - __bfloat162float(hp1.x),
                                                       v.w - __bfloat162float(hp1.y));
            *(unsigned*)&smb[tgt]                 = *(unsigned*)&hp0;
            *(unsigned*)&smb[tgt + 2]             = *(unsigned*)&hp1;
            *(unsigned*)&smb[tgt + AS_LO_OFF]     = *(unsigned*)&lp0;
            *(unsigned*)&smb[tgt + AS_LO_OFF + 2] = *(unsigned*)&lp1;
        }
#pragma unroll
        for (int l = 0; l < 2; l++) {
            int f  = tid + l * 256;
            int kr = f >> 4;
            int c4 = (f & 15) * 4;
            float4 v = pw[l];
            float vv[4] = {v.x, v.y, v.z, v.w};
#pragma unroll
            for (int j = 0; j < 4; j++) {
                __nv_bfloat16 hb = __float2bfloat16(vv[j]);
                __nv_bfloat16 lb = __float2bfloat16(vv[j] - __bfloat162float(hb));
                int idx = boff + BS_OFF + (c4 + j) * PITCH + kr;
                smb[idx]             = hb;
                smb[idx + BS_LO_OFF] = lb;
            }
        }
    };

    auto compute = [&](int bf) {
        const int boff = bf * BUFH;
#pragma unroll
        for (int ks = 0; ks < 2; ks++) {
            const int kb = ks * 16 + 2 * tig;
            unsigned ah[2][4], al[2][4];
#pragma unroll
            for (int mt = 0; mt < 2; mt++) {
                const __nv_bfloat16* ph = &smb[boff + (wm * 32 + mt * 16 + gid) * PITCH + kb];
                ah[mt][0] = *(const unsigned*)(ph);
                ah[mt][1] = *(const unsigned*)(ph + 8 * PITCH);
                ah[mt][2] = *(const unsigned*)(ph + 8);
                ah[mt][3] = *(const unsigned*)(ph + 8 * PITCH + 8);
                al[mt][0] = *(const unsigned*)(ph + AS_LO_OFF);
                al[mt][1] = *(const unsigned*)(ph + AS_LO_OFF + 8 * PITCH);
                al[mt][2] = *(const unsigned*)(ph + AS_LO_OFF + 8);
                al[mt][3] = *(const unsigned*)(ph + AS_LO_OFF + 8 * PITCH + 8);
            }
            unsigned bh[4][2], bl[4][2];
#pragma unroll
            for (int nt = 0; nt < 4; nt++) {
                const __nv_bfloat16* pb = &smb[boff + BS_OFF + (wn * 32 + nt * 8 + gid) * PITCH + kb];
                bh[nt][0] = *(const unsigned*)(pb);
                bh[nt][1] = *(const unsigned*)(pb + 8);
                bl[nt][0] = *(const unsigned*)(pb + BS_LO_OFF);
                bl[nt][1] = *(const unsigned*)(pb + BS_LO_OFF + 8);
            }
#pragma unroll
            for (int mt = 0; mt < 2; mt++)
#pragma unroll
                for (int nt = 0; nt < 4; nt++) {
                    mma16816(c[mt][nt], ah[mt], bh[nt]);
                    mma16816(c[mt][nt], ah[mt], bl[nt]);
                    mma16816(c[mt][nt], al[mt], bh[nt]);
                }
        }
    };

    prefetch(0);
    stage(0);
    __syncthreads();

    int buf = 0;
    for (int kt = 0; kt < NKI; kt++) {
        const bool more = (kt + 1 < NKI);
        if (more) prefetch((kt + 1) * BKK);
        compute(buf);
        if (more) {
            stage(buf ^ 1);
            __syncthreads();
            buf ^= 1;
        }
    }

    // ---------------- epilogue: scores + fp16 V from mma fragments ----------------
    const int h = (col0 >> 5) + wn;       // head of this warp's 32 cols
    const int b = row0 >> 10;

    float2 f1v[4], f2v[4];
#pragma unroll
    for (int nt = 0; nt < 4; nt++) {
        f1v[nt] = *(const float2*)(fc1 + h * D_ + nt * 8 + 2 * tig);
        f2v[nt] = *(const float2*)(fc2 + h * D_ + nt * 8 + 2 * tig);
    }

#pragma unroll
    for (int mt = 0; mt < 2; mt++) {
#pragma unroll
        for (int rr = 0; rr < 2; rr++) {
            const int n = (row0 + wm * 32 + mt * 16 + gid + rr * 8) & (N_ - 1);
            float s1 = 0.f, s2 = 0.f;
#pragma unroll
            for (int nt = 0; nt < 4; nt++) {
                const float cA = c[mt][nt][2 * rr];
                const float cB = c[mt][nt][2 * rr + 1];
                s1 += cA * f1v[nt].x + cB * f1v[nt].y;
                s2 += cA * f2v[nt].x + cB * f2v[nt].y;
                __half2 hv = __floats2half2_rn(cA, cB);
                *(unsigned*)&g_vhalf[((size_t)(b * H_ + h) * N_ + n) * D_ + nt * 8 + 2 * tig] =
                    *(unsigned*)&hv;
            }
            s1 += __shfl_xor_sync(0xffffffffu, s1, 1);
            s2 += __shfl_xor_sync(0xffffffffu, s2, 1);
            s1 += __shfl_xor_sync(0xffffffffu, s1, 2);
            s2 += __shfl_xor_sync(0xffffffffu, s2, 2);
            if (tig == 0) {
                g_self [(b * H_ + h) * N_ + n] = s1;
                g_neigh[(b * H_ + h) * N_ + n] = s2;
            }
        }
    }
}

// ======================= K2: adjacency -> CSR (ballot compaction) =======================
__global__ __launch_bounds__(256) void k_csr(const float* __restrict__ A) {
    int warp = threadIdx.x >> 5;
    int lane = threadIdx.x & 31;
    int row  = blockIdx.x * 8 + warp;

    const float* Arow = A + (size_t)row * N_;
    unsigned short* out = g_idx + (size_t)row * N_;

    int base = 0;
#pragma unroll
    for (int it = 0; it < 8; it++) {
        float4 v = *(const float4*)(Arow + it * 128 + lane * 4);
        float vals[4] = {v.x, v.y, v.z, v.w};
#pragma unroll
        for (int e = 0; e < 4; e++) {
            bool nz = (vals[e] != 0.f);
            unsigned mask = __ballot_sync(0xffffffffu, nz);
            if (nz) {
                int pos = base + __popc(mask & ((1u << lane) - 1u));
                out[pos] = (unsigned short)(it * 128 + lane * 4 + e);
            }
            base += __popc(mask);
        }
    }
    if (lane == 0) g_cnt[row] = base;
}

// ======================= K3: sparse softmax-attention aggregation =======================
// fp16 V tile (64KB, pure copy from g_vhalf) + fp32 neigh scores (4KB) = 68KB smem.
// 384 threads, 3 CTAs/SM. Lane layout: g=lane>>3 picks 1-of-4 edges per step,
// s=lane&7 -> dims [4s,4s+4). (p,m) travel in ONE shfl word.
#define RB 8   // row-blocks per (b,h) -> 128 rows per CTA, grid = 512 CTAs

__global__ __launch_bounds__(384, 3) void k_attn(float* __restrict__ out) {
    extern __shared__ char smraw[];
    __half* Vs = (__half*)smraw;                       // [1024][32] fp16
    float*  ns = (float*)(smraw + N_ * D_ * 2);        // [1024]

    const int b  = blockIdx.z;
    const int h  = blockIdx.y;
    const int rb = blockIdx.x;
    const int tid = threadIdx.x;

    // stage V (pure 64KB copy) + neigh scores
    {
        const uint4* vsrc = (const uint4*)(g_vhalf + (size_t)(b * H_ + h) * N_ * D_);
        uint4* vdst = (uint4*)Vs;
        for (int f = tid; f < N_ * D_ / 8; f += 384) vdst[f] = vsrc[f];
        const float* nsrc = g_neigh + (b * H_ + h) * N_;
        for (int m = tid; m < N_; m += 384) ns[m] = nsrc[m];
    }
    __syncthreads();

    const int warp = tid >> 5;
    const int lane = tid & 31;
    const int g    = lane >> 3;
    const int s    = lane & 7;
    const int rbase = rb * (N_ / RB);

    for (int n = rbase + warp; n < rbase + N_ / RB; n += 12) {
        const int row = b * N_ + n;
        const int nb  = g_cnt[row];
        const float self = g_self[(b * H_ + h) * N_ + n];
        const unsigned short* ip = g_idx + (size_t)row * N_;

        // ---- front: slots 2*lane, 2*lane+1 via one ushort2 load
        const ushort2 mm = *(const ushort2*)(ip + 2 * lane);
        const unsigned m0 = mm.x, m1 = mm.y;
        const bool a0 = (2 * lane < nb);
        const bool a1 = (2 * lane + 1 < nb);
        float p0 = 0.f, p1 = 0.f;
        if (a0) {
            float sc = self + ns[m0];
            sc = (sc >= 0.f) ? sc : 0.01f * sc;
            p0 = __expf(sc);
        }
        if (a1) {
            float sc = self + ns[m1];
            sc = (sc >= 0.f) ? sc : 0.01f * sc;
            p1 = __expf(sc);
        }
        float psum = p0 + p1;
        const unsigned pm0 = a0 ? ((__float_as_uint(p0) & ~1023u) | m0) : 0u;
        const unsigned pm1 = a1 ? ((__float_as_uint(p1) & ~1023u) | m1) : 0u;
        float4 acc = {0.f, 0.f, 0.f, 0.f};

        // ---- rare tail: nb > 64
        for (int base = 64; base < nb; base += 32) {
            unsigned mt = 0;
            float pt = 0.f;
            if (base + lane < nb) {
                mt = ip[base + lane];
                float sc = self + ns[mt];
                sc = (sc >= 0.f) ? sc : 0.01f * sc;
                pt = __expf(sc);
            }
            psum += pt;
            unsigned pmt = (__float_as_uint(pt) & ~1023u) | mt;
#pragma unroll
            for (int t = 0; t < 8; t++) {
                unsigned pmj = __shfl_sync(0xffffffffu, pmt, 4 * t + g);
                float    pj  = __uint_as_float(pmj);
                unsigned mj  = pmj & 1023u;
                uint2 hv = *(const uint2*)(Vs + (mj << 5) + (s << 2));
                float2 f01 = __half22float2(*(__half2*)&hv.x);
                float2 f23 = __half22float2(*(__half2*)&hv.y);
                acc.x = fmaf(pj, f01.x, acc.x);
                acc.y = fmaf(pj, f01.y, acc.y);
                acc.z = fmaf(pj, f23.x, acc.z);
                acc.w = fmaf(pj, f23.y, acc.w);
            }
        }

        // ---- main body: 16 fully-unrolled independent steps, one shfl each
#pragma unroll
        for (int t = 0; t < 8; t++) {
            unsigned pmj = __shfl_sync(0xffffffffu, pm0, 4 * t + g);
            float    pj  = __uint_as_float(pmj);
            unsigned mj  = pmj & 1023u;
            uint2 hv = *(const uint2*)(Vs + (mj << 5) + (s << 2));
            float2 f01 = __half22float2(*(__half2*)&hv.x);
            float2 f23 = __half22float2(*(__half2*)&hv.y);
            acc.x = fmaf(pj, f01.x, acc.x);
            acc.y = fmaf(pj, f01.y, acc.y);
            acc.z = fmaf(pj, f23.x, acc.z);
            acc.w = fmaf(pj, f23.y, acc.w);
        }
#pragma unroll
        for (int t = 0; t < 8; t++) {
            unsigned pmj = __shfl_sync(0xffffffffu, pm1, 4 * t + g);
            float    pj  = __uint_as_float(pmj);
            unsigned mj  = pmj & 1023u;
            uint2 hv = *(const uint2*)(Vs + (mj << 5) + (s << 2));
            float2 f01 = __half22float2(*(__half2*)&hv.x);
            float2 f23 = __half22float2(*(__half2*)&hv.y);
            acc.x = fmaf(pj, f01.x, acc.x);
            acc.y = fmaf(pj, f01.y, acc.y);
            acc.z = fmaf(pj, f23.x, acc.z);
            acc.w = fmaf(pj, f23.y, acc.w);
        }

        // reduce denominator over all 32 lanes
#pragma unroll
        for (int off = 16; off; off >>= 1) psum += __shfl_xor_sync(0xffffffffu, psum, off);
        // reduce acc across the 4 edge-groups (lane bits 3..4)
        acc.x += __shfl_xor_sync(0xffffffffu, acc.x, 8);
        acc.y += __shfl_xor_sync(0xffffffffu, acc.y, 8);
        acc.z += __shfl_xor_sync(0xffffffffu, acc.z, 8);
        acc.w += __shfl_xor_sync(0xffffffffu, acc.w, 8);
        acc.x += __shfl_xor_sync(0xffffffffu, acc.x, 16);
        acc.y += __shfl_xor_sync(0xffffffffu, acc.y, 16);
        acc.z += __shfl_xor_sync(0xffffffffu, acc.z, 16);
        acc.w += __shfl_xor_sync(0xffffffffu, acc.w, 16);

        const float inv = 1.f / psum;
        if (g == 0) {
            float4 o;
            o.x = fmaxf(acc.x * inv, 0.f);
            o.y = fmaxf(acc.y * inv, 0.f);
            o.z = fmaxf(acc.z * inv, 0.f);
            o.w = fmaxf(acc.w * inv, 0.f);
            *(float4*)(out + ((size_t)(b * N_ + n)) * OUT_DIM + h * D_ + 4 * s) = o;
        }
    }
}

// ======================= launch =======================
extern "C" void kernel_launch(void* const* d_in, const int* in_sizes, int n_in,
                              void* d_out, int out_size) {
    const float* A   = (const float*)d_in[0];
    const float* X   = (const float*)d_in[1];
    const float* W   = (const float*)d_in[2];
    const float* fc1 = (const float*)d_in[3];
    const float* fc2 = (const float*)d_in[4];
    float* out = (float*)d_out;

    const int smem_gemm = 2 * BUFH * (int)sizeof(__nv_bfloat16);                 // 61440 B
    const size_t smem_attn = (size_t)N_ * D_ * 2 + (size_t)N_ * sizeof(float);   // 69632 B
    cudaFuncSetAttribute(k_gemm, cudaFuncAttributeMaxDynamicSharedMemorySize, smem_gemm);
    cudaFuncSetAttribute(k_attn, cudaFuncAttributeMaxDynamicSharedMemorySize, (int)smem_attn);

    k_gemm<<<(ROWS_ / BM) * (OUT_DIM / BN), 256, smem_gemm>>>(X, W, fc1, fc2);   // 256 CTAs
    k_csr<<<ROWS_ / 8, 256>>>(A);
    k_attn<<<dim3(RB, H_, B_), 384, smem_attn>>>(out);
}

// round 14
// speedup vs baseline: 1.5810x; 1.0040x over previous
#include <cuda_runtime.h>
#include <cuda_fp16.h>
#include <cuda_bf16.h>

// Problem dims (fixed)
#define B_      8
#define N_      1024
#define IN_DIM  256
#define OUT_DIM 256
#define H_      8
#define D_      32
#define ROWS_   (B_ * N_)          // 8192

// ---------------- static device scratch (no allocations allowed) ----------------
__device__ __half          g_vhalf[(size_t)B_ * H_ * N_ * D_];  // 4MB: fp16 V, head-major
__device__ float           g_self[B_ * H_ * N_];                // [b][h][n]
__device__ float           g_neigh[B_ * H_ * N_];               // [b][h][n]
__device__ unsigned short  g_idx[(size_t)ROWS_ * N_];           // 16MB CSR cols (fixed stride)
__device__ int             g_cnt[ROWS_];

// ======================= K1: split-bf16 tensor-core GEMM + scores/V epilogue ==========
// inputs = X@W via 3x bf16 mma (hi*hi + hi*lo + lo*hi), fp32 accum: ~1.5e-5 rel err.
// CTA 128x64 (256 CTAs, full wave), 8 warps, warp tile 32x32 (one head per warp).
// Fragments loaded via ldmatrix.m8n8.x4 (PITCH=40 halves -> 8-row groups hit
// distinct banks: stride 20 words). K=32 double-buffered smem.
#define BM 128
#define BN 64
#define BKK 32
#define NKI (IN_DIM / BKK)   // 8
#define PITCH 40
#define BUFH  15360          // halves per buffer: (128+128+64+64)*40
#define AS_LO_OFF 5120
#define BS_OFF    10240
#define BS_LO_OFF 2560

__device__ __forceinline__ void mma16816(float* c, const unsigned* a, const unsigned* b) {
    asm volatile(
        "mma.sync.aligned.m16n8k16.row.col.f32.bf16.bf16.f32 "
        "{%0,%1,%2,%3}, {%4,%5,%6,%7}, {%8,%9}, {%0,%1,%2,%3};\n"
        : "+f"(c[0]), "+f"(c[1]), "+f"(c[2]), "+f"(c[3])
        : "r"(a[0]), "r"(a[1]), "r"(a[2]), "r"(a[3]), "r"(b[0]), "r"(b[1]));
}

__device__ __forceinline__ void ldm_x4(unsigned* r, unsigned saddr) {
    asm volatile(
        "ldmatrix.sync.aligned.m8n8.x4.shared.b16 {%0,%1,%2,%3}, [%4];\n"
        : "=r"(r[0]), "=r"(r[1]), "=r"(r[2]), "=r"(r[3]) : "r"(saddr));
}

__global__ __launch_bounds__(256, 2) void k_gemm(const float* __restrict__ X,
                                                 const float* __restrict__ W,
                                                 const float* __restrict__ fc1,
                                                 const float* __restrict__ fc2) {
    extern __shared__ __nv_bfloat16 smb[];

    const int tid  = threadIdx.x;
    const int row0 = (blockIdx.x >> 2) * BM;
    const int col0 = (blockIdx.x & 3) * BN;
    const int warp = tid >> 5;
    const int lane = tid & 31;
    const int wm   = warp >> 1;          // 0..3  (32-row warp tile)
    const int wn   = warp & 1;           // 0..1  (32-col warp tile = 1 head)
    const int gid  = lane >> 2;          // 0..7
    const int tig  = lane & 3;           // 0..3

    const unsigned sbase = (unsigned)__cvta_generic_to_shared(smb);
    // ldmatrix lane->row maps (half-offsets within a buffer)
    const int l7  = lane & 7;
    const int lb3 = (lane >> 3) & 1;
    const int lb4 = (lane >> 4) & 1;
    const unsigned a_lane = (unsigned)((wm * 32 + lb3 * 8 + l7) * PITCH + lb4 * 8);
    const unsigned b_lane = (unsigned)(BS_OFF + (wn * 32 + lb4 * 8 + l7) * PITCH + lb3 * 8);

    float c[2][4][4];
#pragma unroll
    for (int mt = 0; mt < 2; mt++)
#pragma unroll
        for (int nt = 0; nt < 4; nt++)
#pragma unroll
            for (int q = 0; q < 4; q++) c[mt][nt][q] = 0.f;

    float4 pa[4], pw[2];

    auto prefetch = [&](int k0) {
#pragma unroll
        for (int l = 0; l < 4; l++) {
            int f = tid + l * 256;
            pa[l] = *(const float4*)(X + (size_t)(row0 + (f >> 3)) * IN_DIM + k0 + (f & 7) * 4);
        }
#pragma unroll
        for (int l = 0; l < 2; l++) {
            int f = tid + l * 256;
            pw[l] = *(const float4*)(W + (size_t)(k0 + (f >> 4)) * OUT_DIM + col0 + (f & 15) * 4);
        }
    };

    auto stage = [&](int nb) {
        const int boff = nb * BUFH;
#pragma unroll
        for (int l = 0; l < 4; l++) {
            int f = tid + l * 256;
            int tgt = boff + (f >> 3) * PITCH + (f & 7) * 4;
            float4 v = pa[l];
            __nv_bfloat162 hp0 = __floats2bfloat162_rn(v.x, v.y);
            __nv_bfloat162 hp1 = __floats2bfloat162_rn(v.z, v.w);
            __nv_bfloat162 lp0 = __floats2bfloat162_rn(v.x - __bfloat162float(hp0.x),
                                                       v.y - __bfloat162float(hp0.y));
            __nv_bfloat162 lp1 = __floats2bfloat162_rn(v.z - __bfloat162float(hp1.x),
                                                       v.w - __bfloat162float(hp1.y));
            *(unsigned*)&smb[tgt]                 = *(unsigned*)&hp0;
            *(unsigned*)&smb[tgt + 2]             = *(unsigned*)&hp1;
            *(unsigned*)&smb[tgt + AS_LO_OFF]     = *(unsigned*)&lp0;
            *(unsigned*)&smb[tgt + AS_LO_OFF + 2] = *(unsigned*)&lp1;
        }
#pragma unroll
        for (int l = 0; l < 2; l++) {
            int f  = tid + l * 256;
            int kr = f >> 4;
            int c4 = (f & 15) * 4;
            float4 v = pw[l];
            float vv[4] = {v.x, v.y, v.z, v.w};
#pragma unroll
            for (int j = 0; j < 4; j++) {
                __nv_bfloat16 hb = __float2bfloat16(vv[j]);
                __nv_bfloat16 lb = __float2bfloat16(vv[j] - __bfloat162float(hb));
                int idx = boff + BS_OFF + (c4 + j) * PITCH + kr;
                smb[idx]             = hb;
                smb[idx + BS_LO_OFF] = lb;
            }
        }
    };

    auto compute = [&](int bf) {
#pragma unroll
        for (int ks = 0; ks < 2; ks++) {
            const unsigned ka = (unsigned)(bf * BUFH + ks * 16);
            unsigned ah[2][4], al[2][4];
#pragma unroll
            for (int mt = 0; mt < 2; mt++) {
                const unsigned abase = sbase + 2u * (ka + a_lane + mt * 16 * PITCH);
                ldm_x4(ah[mt], abase);
                ldm_x4(al[mt], abase + 2u * AS_LO_OFF);
            }
            unsigned bh[4][2], bl[4][2], rt[4];
#pragma unroll
            for (int pr = 0; pr < 2; pr++) {
                const unsigned bbase = sbase + 2u * (ka + b_lane + pr * 16 * PITCH);
                ldm_x4(rt, bbase);
                bh[2 * pr][0] = rt[0]; bh[2 * pr][1] = rt[1];
                bh[2 * pr + 1][0] = rt[2]; bh[2 * pr + 1][1] = rt[3];
                ldm_x4(rt, bbase + 2u * BS_LO_OFF);
                bl[2 * pr][0] = rt[0]; bl[2 * pr][1] = rt[1];
                bl[2 * pr + 1][0] = rt[2]; bl[2 * pr + 1][1] = rt[3];
            }
#pragma unroll
            for (int mt = 0; mt < 2; mt++)
#pragma unroll
                for (int nt = 0; nt < 4; nt++) {
                    mma16816(c[mt][nt], ah[mt], bh[nt]);
                    mma16816(c[mt][nt], ah[mt], bl[nt]);
                    mma16816(c[mt][nt], al[mt], bh[nt]);
                }
        }
    };

    prefetch(0);
    stage(0);
    __syncthreads();

    int buf = 0;
    for (int kt = 0; kt < NKI; kt++) {
        const bool more = (kt + 1 < NKI);
        if (more) prefetch((kt + 1) * BKK);
        compute(buf);
        if (more) {
            stage(buf ^ 1);
            __syncthreads();
            buf ^= 1;
        }
    }

    // ---------------- epilogue: scores + fp16 V from mma fragments ----------------
    const int h = (col0 >> 5) + wn;       // head of this warp's 32 cols
    const int b = row0 >> 10;

    float2 f1v[4], f2v[4];
#pragma unroll
    for (int nt = 0; nt < 4; nt++) {
        f1v[nt] = *(const float2*)(fc1 + h * D_ + nt * 8 + 2 * tig);
        f2v[nt] = *(const float2*)(fc2 + h * D_ + nt * 8 + 2 * tig);
    }

#pragma unroll
    for (int mt = 0; mt < 2; mt++) {
#pragma unroll
        for (int rr = 0; rr < 2; rr++) {
            const int n = (row0 + wm * 32 + mt * 16 + gid + rr * 8) & (N_ - 1);
            float s1 = 0.f, s2 = 0.f;
#pragma unroll
            for (int nt = 0; nt < 4; nt++) {
                const float cA = c[mt][nt][2 * rr];
                const float cB = c[mt][nt][2 * rr + 1];
                s1 += cA * f1v[nt].x + cB * f1v[nt].y;
                s2 += cA * f2v[nt].x + cB * f2v[nt].y;
                __half2 hv = __floats2half2_rn(cA, cB);
                *(unsigned*)&g_vhalf[((size_t)(b * H_ + h) * N_ + n) * D_ + nt * 8 + 2 * tig] =
                    *(unsigned*)&hv;
            }
            s1 += __shfl_xor_sync(0xffffffffu, s1, 1);
            s2 += __shfl_xor_sync(0xffffffffu, s2, 1);
            s1 += __shfl_xor_sync(0xffffffffu, s1, 2);
            s2 += __shfl_xor_sync(0xffffffffu, s2, 2);
            if (tig == 0) {
                g_self [(b * H_ + h) * N_ + n] = s1;
                g_neigh[(b * H_ + h) * N_ + n] = s2;
            }
        }
    }
}

// ======================= K2: adjacency -> CSR (ballot compaction) =======================
__global__ __launch_bounds__(256) void k_csr(const float* __restrict__ A) {
    int warp = threadIdx.x >> 5;
    int lane = threadIdx.x & 31;
    int row  = blockIdx.x * 8 + warp;

    const float* Arow = A + (size_t)row * N_;
    unsigned short* out = g_idx + (size_t)row * N_;

    int base = 0;
#pragma unroll
    for (int it = 0; it < 8; it++) {
        float4 v = *(const float4*)(Arow + it * 128 + lane * 4);
        float vals[4] = {v.x, v.y, v.z, v.w};
#pragma unroll
        for (int e = 0; e < 4; e++) {
            bool nz = (vals[e] != 0.f);
            unsigned mask = __ballot_sync(0xffffffffu, nz);
            if (nz) {
                int pos = base + __popc(mask & ((1u << lane) - 1u));
                out[pos] = (unsigned short)(it * 128 + lane * 4 + e);
            }
            base += __popc(mask);
        }
    }
    if (lane == 0) g_cnt[row] = base;
}

// ======================= K3: sparse softmax-attention aggregation =======================
// fp16 V tile (64KB, pure copy from g_vhalf) + fp32 neigh scores (4KB) = 68KB smem.
// 384 threads, 3 CTAs/SM. Lane layout: g=lane>>3 picks 1-of-4 edges per step,
// s=lane&7 -> dims [4s,4s+4). (p,m) travel in ONE shfl word.
#define RB 8   // row-blocks per (b,h) -> 128 rows per CTA, grid = 512 CTAs

__global__ __launch_bounds__(384, 3) void k_attn(float* __restrict__ out) {
    extern __shared__ char smraw[];
    __half* Vs = (__half*)smraw;                       // [1024][32] fp16
    float*  ns = (float*)(smraw + N_ * D_ * 2);        // [1024]

    const int b  = blockIdx.z;
    const int h  = blockIdx.y;
    const int rb = blockIdx.x;
    const int tid = threadIdx.x;

    // stage V (pure 64KB copy) + neigh scores
    {
        const uint4* vsrc = (const uint4*)(g_vhalf + (size_t)(b * H_ + h) * N_ * D_);
        uint4* vdst = (uint4*)Vs;
        for (int f = tid; f < N_ * D_ / 8; f += 384) vdst[f] = vsrc[f];
        const float* nsrc = g_neigh + (b * H_ + h) * N_;
        for (int m = tid; m < N_; m += 384) ns[m] = nsrc[m];
    }
    __syncthreads();

    const int warp = tid >> 5;
    const int lane = tid & 31;
    const int g    = lane >> 3;
    const int s    = lane & 7;
    const int rbase = rb * (N_ / RB);

    for (int n = rbase + warp; n < rbase + N_ / RB; n += 12) {
        const int row = b * N_ + n;
        const int nb  = g_cnt[row];
        const float self = g_self[(b * H_ + h) * N_ + n];
        const unsigned short* ip = g_idx + (size_t)row * N_;

        // ---- front: slots 2*lane, 2*lane+1 via one ushort2 load
        const ushort2 mm = *(const ushort2*)(ip + 2 * lane);
        const unsigned m0 = mm.x, m1 = mm.y;
        const bool a0 = (2 * lane < nb);
        const bool a1 = (2 * lane + 1 < nb);
        float p0 = 0.f, p1 = 0.f;
        if (a0) {
            float sc = self + ns[m0];
            sc = (sc >= 0.f) ? sc : 0.01f * sc;
            p0 = __expf(sc);
        }
        if (a1) {
            float sc = self + ns[m1];
            sc = (sc >= 0.f) ? sc : 0.01f * sc;
            p1 = __expf(sc);
        }
        float psum = p0 + p1;
        const unsigned pm0 = a0 ? ((__float_as_uint(p0) & ~1023u) | m0) : 0u;
        const unsigned pm1 = a1 ? ((__float_as_uint(p1) & ~1023u) | m1) : 0u;
        float4 acc = {0.f, 0.f, 0.f, 0.f};

        // ---- rare tail: nb > 64
        for (int base = 64; base < nb; base += 32) {
            unsigned mt = 0;
            float pt = 0.f;
            if (base + lane < nb) {
                mt = ip[base + lane];
                float sc = self + ns[mt];
                sc = (sc >= 0.f) ? sc : 0.01f * sc;
                pt = __expf(sc);
            }
            psum += pt;
            unsigned pmt = (__float_as_uint(pt) & ~1023u) | mt;
#pragma unroll
            for (int t = 0; t < 8; t++) {
                unsigned pmj = __shfl_sync(0xffffffffu, pmt, 4 * t + g);
                float    pj  = __uint_as_float(pmj);
                unsigned mj  = pmj & 1023u;
                uint2 hv = *(const uint2*)(Vs + (mj << 5) + (s << 2));
                float2 f01 = __half22float2(*(__half2*)&hv.x);
                float2 f23 = __half22float2(*(__half2*)&hv.y);
                acc.x = fmaf(pj, f01.x, acc.x);
                acc.y = fmaf(pj, f01.y, acc.y);
                acc.z = fmaf(pj, f23.x, acc.z);
                acc.w = fmaf(pj, f23.y, acc.w);
            }
        }

        // ---- main body: 16 fully-unrolled independent steps, one shfl each
#pragma unroll
        for (int t = 0; t < 8; t++) {
            unsigned pmj = __shfl_sync(0xffffffffu, pm0, 4 * t + g);
            float    pj  = __uint_as_float(pmj);
            unsigned mj  = pmj & 1023u;
            uint2 hv = *(const uint2*)(Vs + (mj << 5) + (s << 2));
            float2 f01 = __half22float2(*(__half2*)&hv.x);
            float2 f23 = __half22float2(*(__half2*)&hv.y);
            acc.x = fmaf(pj, f01.x, acc.x);
            acc.y = fmaf(pj, f01.y, acc.y);
            acc.z = fmaf(pj, f23.x, acc.z);
            acc.w = fmaf(pj, f23.y, acc.w);
        }
#pragma unroll
        for (int t = 0; t < 8; t++) {
            unsigned pmj = __shfl_sync(0xffffffffu, pm1, 4 * t + g);
            float    pj  = __uint_as_float(pmj);
            unsigned mj  = pmj & 1023u;
            uint2 hv = *(const uint2*)(Vs + (mj << 5) + (s << 2));
            float2 f01 = __half22float2(*(__half2*)&hv.x);
            float2 f23 = __half22float2(*(__half2*)&hv.y);
            acc.x = fmaf(pj, f01.x, acc.x);
            acc.y = fmaf(pj, f01.y, acc.y);
            acc.z = fmaf(pj, f23.x, acc.z);
            acc.w = fmaf(pj, f23.y, acc.w);
        }

        // reduce denominator over all 32 lanes
#pragma unroll
        for (int off = 16; off; off >>= 1) psum += __shfl_xor_sync(0xffffffffu, psum, off);
        // reduce acc across the 4 edge-groups (lane bits 3..4)
        acc.x += __shfl_xor_sync(0xffffffffu, acc.x, 8);
        acc.y += __shfl_xor_sync(0xffffffffu, acc.y, 8);
        acc.z += __shfl_xor_sync(0xffffffffu, acc.z, 8);
        acc.w += __shfl_xor_sync(0xffffffffu, acc.w, 8);
        acc.x += __shfl_xor_sync(0xffffffffu, acc.x, 16);
        acc.y += __shfl_xor_sync(0xffffffffu, acc.y, 16);
        acc.z += __shfl_xor_sync(0xffffffffu, acc.z, 16);
        acc.w += __shfl_xor_sync(0xffffffffu, acc.w, 16);

        const float inv = 1.f / psum;
        if (g == 0) {
            float4 o;
            o.x = fmaxf(acc.x * inv, 0.f);
            o.y = fmaxf(acc.y * inv, 0.f);
            o.z = fmaxf(acc.z * inv, 0.f);
            o.w = fmaxf(acc.w * inv, 0.f);
            *(float4*)(out + ((size_t)(b * N_ + n)) * OUT_DIM + h * D_ + 4 * s) = o;
        }
    }
}

// ======================= launch =======================
extern "C" void kernel_launch(void* const* d_in, const int* in_sizes, int n_in,
                              void* d_out, int out_size) {
    const float* A   = (const float*)d_in[0];
    const float* X   = (const float*)d_in[1];
    const float* W   = (const float*)d_in[2];
    const float* fc1 = (const float*)d_in[3];
    const float* fc2 = (const float*)d_in[4];
    float* out = (float*)d_out;

    const int smem_gemm = 2 * BUFH * (int)sizeof(__nv_bfloat16);                 // 61440 B
    const size_t smem_attn = (size_t)N_ * D_ * 2 + (size_t)N_ * sizeof(float);   // 69632 B
    cudaFuncSetAttribute(k_gemm, cudaFuncAttributeMaxDynamicSharedMemorySize, smem_gemm);
    cudaFuncSetAttribute(k_attn, cudaFuncAttributeMaxDynamicSharedMemorySize, (int)smem_attn);

    k_gemm<<<(ROWS_ / BM) * (OUT_DIM / BN), 256, smem_gemm>>>(X, W, fc1, fc2);   // 256 CTAs
    k_csr<<<ROWS_ / 8, 256>>>(A);
    k_attn<<<dim3(RB, H_, B_), 384, smem_attn>>>(out);
}

// round 16
// speedup vs baseline: 1.7456x; 1.1041x over previous
#include <cuda_runtime.h>
#include <cuda_fp16.h>
#include <cuda_bf16.h>

// Problem dims (fixed)
#define B_      8
#define N_      1024
#define IN_DIM  256
#define OUT_DIM 256
#define H_      8
#define D_      32
#define ROWS_   (B_ * N_)          // 8192

// ---------------- static device scratch (no allocations allowed) ----------------
__device__ __nv_bfloat16   g_xhi[(size_t)ROWS_ * IN_DIM];       // 4MB  X hi, [row][k]
__device__ __nv_bfloat16   g_xlo[(size_t)ROWS_ * IN_DIM];       // 4MB  X lo
__device__ __nv_bfloat16   g_whiT[OUT_DIM * IN_DIM];            // 128KB W hi, [n][k]
__device__ __nv_bfloat16   g_wloT[OUT_DIM * IN_DIM];            // 128KB W lo, [n][k]
__device__ __half          g_vhalf[(size_t)B_ * H_ * N_ * D_];  // 4MB: fp16 V, head-major
__device__ float           g_self[B_ * H_ * N_];                // [b][h][n]
__device__ float           g_neigh[B_ * H_ * N_];               // [b][h][n]
__device__ unsigned short  g_idx[(size_t)ROWS_ * N_];           // 16MB CSR cols (fixed stride)
__device__ int             g_cnt[ROWS_];

// ======================= K0: prep = CSR build + X/W bf16 split =======================
// blocks [0,1024): adjacency->CSR (8 rows each)
// blocks [1024,2048): X split -> g_xhi/g_xlo (8 X-rows each)
// blocks [2048,2080): W split+transpose -> g_whiT/g_wloT (8 k-rows each)
__global__ __launch_bounds__(256) void k_prep(const float* __restrict__ A,
                                              const float* __restrict__ X,
                                              const float* __restrict__ W) {
    __shared__ float slab[8][256];
    const int bx = blockIdx.x;
    const int t  = threadIdx.x;

    if (bx < 1024) {
        // ---- CSR branch (warp per row; A entries exactly 0.0/1.0)
        int warp = t >> 5;
        int lane = t & 31;
        int row  = bx * 8 + warp;
        const float* Arow = A + (size_t)row * N_;
        unsigned short* out = g_idx + (size_t)row * N_;
        int base = 0;
#pragma unroll
        for (int it = 0; it < 8; it++) {
            float4 v = *(const float4*)(Arow + it * 128 + lane * 4);
            float vals[4] = {v.x, v.y, v.z, v.w};
#pragma unroll
            for (int e = 0; e < 4; e++) {
                bool nz = (vals[e] != 0.f);
                unsigned mask = __ballot_sync(0xffffffffu, nz);
                if (nz) {
                    int pos = base + __popc(mask & ((1u << lane) - 1u));
                    out[pos] = (unsigned short)(it * 128 + lane * 4 + e);
                }
                base += __popc(mask);
            }
        }
        if (lane == 0) g_cnt[row] = base;
    } else if (bx < 2048) {
        // ---- X split: 8 consecutive floats per thread
        const size_t base = ((size_t)(bx - 1024) * 2048) + (size_t)t * 8;
        float4 v0 = *(const float4*)(X + base);
        float4 v1 = *(const float4*)(X + base + 4);
        float vv[8] = {v0.x, v0.y, v0.z, v0.w, v1.x, v1.y, v1.z, v1.w};
        __nv_bfloat16 hi[8], lo[8];
#pragma unroll
        for (int j = 0; j < 8; j++) {
            hi[j] = __float2bfloat16(vv[j]);
            lo[j] = __float2bfloat16(vv[j] - __bfloat162float(hi[j]));
        }
        *(uint4*)(g_xhi + base) = *(uint4*)hi;
        *(uint4*)(g_xlo + base) = *(uint4*)lo;
    } else {
        // ---- W split + transpose: slab of 8 k-rows, write [n][k]
        const int k0 = (bx - 2048) * 8;
#pragma unroll
        for (int i = 0; i < 8; i++) {
            int f = t + i * 256;
            slab[f >> 8][f & 255] = W[(size_t)(k0 + (f >> 8)) * OUT_DIM + (f & 255)];
        }
        __syncthreads();
        const int n = t;
        __nv_bfloat16 hi[8], lo[8];
#pragma unroll
        for (int k = 0; k < 8; k++) {
            float w = slab[k][n];
            hi[k] = __float2bfloat16(w);
            lo[k] = __float2bfloat16(w - __bfloat162float(hi[k]));
        }
        *(uint4*)(g_whiT + (size_t)n * IN_DIM + k0) = *(uint4*)hi;
        *(uint4*)(g_wloT + (size_t)n * IN_DIM + k0) = *(uint4*)lo;
    }
}

// ======================= K1: split-bf16 tensor-core GEMM + scores/V epilogue ==========
// inputs = X@W via 3x bf16 mma (hi*hi + hi*lo + lo*hi), fp32 accum.
// CTA 128x64 (256 CTAs), 8 warps, warp tile 32x32 (one head per warp).
// cp.async 3-stage pipeline from pre-split bf16 arrays; ldmatrix fragment loads.
#define BM 128
#define BN 64
#define BKK 32
#define NKI (IN_DIM / BKK)   // 8
#define PITCH 40
#define BUFH  15360          // halves per stage: (128+128+64+64)*40
#define AS_LO_OFF 5120
#define BS_OFF    10240
#define BS_LO_OFF 2560
#define NSTAGE 3

__device__ __forceinline__ void mma16816(float* c, const unsigned* a, const unsigned* b) {
    asm volatile(
        "mma.sync.aligned.m16n8k16.row.col.f32.bf16.bf16.f32 "
        "{%0,%1,%2,%3}, {%4,%5,%6,%7}, {%8,%9}, {%0,%1,%2,%3};\n"
        : "+f"(c[0]), "+f"(c[1]), "+f"(c[2]), "+f"(c[3])
        : "r"(a[0]), "r"(a[1]), "r"(a[2]), "r"(a[3]), "r"(b[0]), "r"(b[1]));
}

__device__ __forceinline__ void ldm_x4(unsigned* r, unsigned saddr) {
    asm volatile(
        "ldmatrix.sync.aligned.m8n8.x4.shared.b16 {%0,%1,%2,%3}, [%4];\n"
        : "=r"(r[0]), "=r"(r[1]), "=r"(r[2]), "=r"(r[3]) : "r"(saddr));
}

__device__ __forceinline__ void cp16(unsigned dst, const void* src) {
    asm volatile("cp.async.cg.shared.global [%0], [%1], 16;\n" :: "r"(dst), "l"(src));
}

__global__ __launch_bounds__(256, 2) void k_gemm(const float* __restrict__ fc1,
                                                 const float* __restrict__ fc2) {
    extern __shared__ __nv_bfloat16 smb[];

    const int tid  = threadIdx.x;
    const int row0 = (blockIdx.x >> 2) * BM;
    const int col0 = (blockIdx.x & 3) * BN;
    const int warp = tid >> 5;
    const int lane = tid & 31;
    const int wm   = warp >> 1;          // 0..3  (32-row warp tile)
    const int wn   = warp & 1;           // 0..1  (32-col warp tile = 1 head)
    const int gid  = lane >> 2;          // 0..7
    const int tig  = lane & 3;           // 0..3

    const unsigned sbase = (unsigned)__cvta_generic_to_shared(smb);
    // ldmatrix lane->row maps (half-offsets within a stage)
    const int l7  = lane & 7;
    const int lb3 = (lane >> 3) & 1;
    const int lb4 = (lane >> 4) & 1;
    const unsigned a_lane = (unsigned)((wm * 32 + lb3 * 8 + l7) * PITCH + lb4 * 8);
    const unsigned b_lane = (unsigned)(BS_OFF + (wn * 32 + lb4 * 8 + l7) * PITCH + lb3 * 8);

    // per-thread cp.async mapping (6 chunks: 4 A-chunks, 2 B-chunks), loop-invariant
    const __nv_bfloat16* csrc[6];
    unsigned cdst[6];   // half-offset within a stage
#pragma unroll
    for (int l = 0; l < 6; l++) {
        int c = tid + l * 256;
        if (c < 1024) {
            int r = c >> 2, q = c & 3;
            csrc[l] = (r < 128 ? g_xhi : g_xlo) + (size_t)(row0 + (r & 127)) * IN_DIM + q * 8;
            cdst[l] = (unsigned)((r < 128 ? r * PITCH : AS_LO_OFF + (r - 128) * PITCH) + q * 8);
        } else {
            int cb = c - 1024;
            int r = cb >> 2, q = cb & 3;
            csrc[l] = (r < 64 ? g_whiT : g_wloT) + (size_t)(col0 + (r & 63)) * IN_DIM + q * 8;
            cdst[l] = (unsigned)(BS_OFF + (r < 64 ? r * PITCH : BS_LO_OFF + (r - 64) * PITCH) + q * 8);
        }
    }

    auto issue_stage = [&](int st) {
        const unsigned soff = (unsigned)((st % NSTAGE) * BUFH);
        const int k0 = st * BKK;
#pragma unroll
        for (int l = 0; l < 6; l++)
            cp16(sbase + 2u * (soff + cdst[l]), csrc[l] + k0);
    };

    float c[2][4][4];
#pragma unroll
    for (int mt = 0; mt < 2; mt++)
#pragma unroll
        for (int nt = 0; nt < 4; nt++)
#pragma unroll
            for (int q = 0; q < 4; q++) c[mt][nt][q] = 0.f;

    issue_stage(0);
    asm volatile("cp.async.commit_group;\n");
    issue_stage(1);
    asm volatile("cp.async.commit_group;\n");

    for (int kt = 0; kt < NKI; kt++) {
        asm volatile("cp.async.wait_group 1;\n");
        __syncthreads();
        if (kt + 2 < NKI) issue_stage(kt + 2);
        asm volatile("cp.async.commit_group;\n");

        const unsigned boff = (unsigned)((kt % NSTAGE) * BUFH);
#pragma unroll
        for (int ks = 0; ks < 2; ks++) {
            const unsigned ka = boff + ks * 16;
            unsigned ah[2][4], al[2][4];
#pragma unroll
            for (int mt = 0; mt < 2; mt++) {
                const unsigned abase = sbase + 2u * (ka + a_lane + mt * 16 * PITCH);
                ldm_x4(ah[mt], abase);
                ldm_x4(al[mt], abase + 2u * AS_LO_OFF);
            }
            unsigned bh[4][2], bl[4][2], rt[4];
#pragma unroll
            for (int pr = 0; pr < 2; pr++) {
                const unsigned bbase = sbase + 2u * (ka + b_lane + pr * 16 * PITCH);
                ldm_x4(rt, bbase);
                bh[2 * pr][0] = rt[0]; bh[2 * pr][1] = rt[1];
                bh[2 * pr + 1][0] = rt[2]; bh[2 * pr + 1][1] = rt[3];
                ldm_x4(rt, bbase + 2u * BS_LO_OFF);
                bl[2 * pr][0] = rt[0]; bl[2 * pr][1] = rt[1];
                bl[2 * pr + 1][0] = rt[2]; bl[2 * pr + 1][1] = rt[3];
            }
#pragma unroll
            for (int mt = 0; mt < 2; mt++)
#pragma unroll
                for (int nt = 0; nt < 4; nt++) {
                    mma16816(c[mt][nt], ah[mt], bh[nt]);
                    mma16816(c[mt][nt], ah[mt], bl[nt]);
                    mma16816(c[mt][nt], al[mt], bh[nt]);
                }
        }
    }

    // ---------------- epilogue: scores + fp16 V from mma fragments ----------------
    const int h = (col0 >> 5) + wn;       // head of this warp's 32 cols
    const int b = row0 >> 10;

    float2 f1v[4], f2v[4];
#pragma unroll
    for (int nt = 0; nt < 4; nt++) {
        f1v[nt] = *(const float2*)(fc1 + h * D_ + nt * 8 + 2 * tig);
        f2v[nt] = *(const float2*)(fc2 + h * D_ + nt * 8 + 2 * tig);
    }

#pragma unroll
    for (int mt = 0; mt < 2; mt++) {
#pragma unroll
        for (int rr = 0; rr < 2; rr++) {
            const int n = (row0 + wm * 32 + mt * 16 + gid + rr * 8) & (N_ - 1);
            float s1 = 0.f, s2 = 0.f;
#pragma unroll
            for (int nt = 0; nt < 4; nt++) {
                const float cA = c[mt][nt][2 * rr];
                const float cB = c[mt][nt][2 * rr + 1];
                s1 += cA * f1v[nt].x + cB * f1v[nt].y;
                s2 += cA * f2v[nt].x + cB * f2v[nt].y;
                __half2 hv = __floats2half2_rn(cA, cB);
                *(unsigned*)&g_vhalf[((size_t)(b * H_ + h) * N_ + n) * D_ + nt * 8 + 2 * tig] =
                    *(unsigned*)&hv;
            }
            s1 += __shfl_xor_sync(0xffffffffu, s1, 1);
            s2 += __shfl_xor_sync(0xffffffffu, s2, 1);
            s1 += __shfl_xor_sync(0xffffffffu, s1, 2);
            s2 += __shfl_xor_sync(0xffffffffu, s2, 2);
            if (tig == 0) {
                g_self [(b * H_ + h) * N_ + n] = s1;
                g_neigh[(b * H_ + h) * N_ + n] = s2;
            }
        }
    }
}

// ======================= K3: sparse softmax-attention aggregation =======================
// fp16 V tile (64KB, pure copy from g_vhalf) + fp32 neigh scores (4KB) = 68KB smem.
// 384 threads, 3 CTAs/SM. Lane layout: g=lane>>3 picks 1-of-4 edges per step,
// s=lane&7 -> dims [4s,4s+4). (p,m) travel in ONE shfl word.
#define RB 8   // row-blocks per (b,h) -> 128 rows per CTA, grid = 512 CTAs

__global__ __launch_bounds__(384, 3) void k_attn(float* __restrict__ out) {
    extern __shared__ char smraw[];
    __half* Vs = (__half*)smraw;                       // [1024][32] fp16
    float*  ns = (float*)(smraw + N_ * D_ * 2);        // [1024]

    const int b  = blockIdx.z;
    const int h  = blockIdx.y;
    const int rb = blockIdx.x;
    const int tid = threadIdx.x;

    // stage V (pure 64KB copy) + neigh scores
    {
        const uint4* vsrc = (const uint4*)(g_vhalf + (size_t)(b * H_ + h) * N_ * D_);
        uint4* vdst = (uint4*)Vs;
        for (int f = tid; f < N_ * D_ / 8; f += 384) vdst[f] = vsrc[f];
        const float* nsrc = g_neigh + (b * H_ + h) * N_;
        for (int m = tid; m < N_; m += 384) ns[m] = nsrc[m];
    }
    __syncthreads();

    const int warp = tid >> 5;
    const int lane = tid & 31;
    const int g    = lane >> 3;
    const int s    = lane & 7;
    const int rbase = rb * (N_ / RB);

    for (int n = rbase + warp; n < rbase + N_ / RB; n += 12) {
        const int row = b * N_ + n;
        const int nb  = g_cnt[row];
        const float self = g_self[(b * H_ + h) * N_ + n];
        const unsigned short* ip = g_idx + (size_t)row * N_;

        // ---- front: slots 2*lane, 2*lane+1 via one ushort2 load
        const ushort2 mm = *(const ushort2*)(ip + 2 * lane);
        const unsigned m0 = mm.x, m1 = mm.y;
        const bool a0 = (2 * lane < nb);
        const bool a1 = (2 * lane + 1 < nb);
        float p0 = 0.f, p1 = 0.f;
        if (a0) {
            float sc = self + ns[m0];
            sc = (sc >= 0.f) ? sc : 0.01f * sc;
            p0 = __expf(sc);
        }
        if (a1) {
            float sc = self + ns[m1];
            sc = (sc >= 0.f) ? sc : 0.01f * sc;
            p1 = __expf(sc);
        }
        float psum = p0 + p1;
        const unsigned pm0 = a0 ? ((__float_as_uint(p0) & ~1023u) | m0) : 0u;
        const unsigned pm1 = a1 ? ((__float_as_uint(p1) & ~1023u) | m1) : 0u;
        float4 acc = {0.f, 0.f, 0.f, 0.f};

        // ---- rare tail: nb > 64
        for (int base = 64; base < nb; base += 32) {
            unsigned mt = 0;
            float pt = 0.f;
            if (base + lane < nb) {
                mt = ip[base + lane];
                float sc = self + ns[mt];
                sc = (sc >= 0.f) ? sc : 0.01f * sc;
                pt = __expf(sc);
            }
            psum += pt;
            unsigned pmt = (__float_as_uint(pt) & ~1023u) | mt;
#pragma unroll
            for (int t = 0; t < 8; t++) {
                unsigned pmj = __shfl_sync(0xffffffffu, pmt, 4 * t + g);
                float    pj  = __uint_as_float(pmj);
                unsigned mj  = pmj & 1023u;
                uint2 hv = *(const uint2*)(Vs + (mj << 5) + (s << 2));
                float2 f01 = __half22float2(*(__half2*)&hv.x);
                float2 f23 = __half22float2(*(__half2*)&hv.y);
                acc.x = fmaf(pj, f01.x, acc.x);
                acc.y = fmaf(pj, f01.y, acc.y);
                acc.z = fmaf(pj, f23.x, acc.z);
                acc.w = fmaf(pj, f23.y, acc.w);
            }
        }

        // ---- main body: 16 fully-unrolled independent steps, one shfl each
#pragma unroll
        for (int t = 0; t < 8; t++) {
            unsigned pmj = __shfl_sync(0xffffffffu, pm0, 4 * t + g);
            float    pj  = __uint_as_float(pmj);
            unsigned mj  = pmj & 1023u;
            uint2 hv = *(const uint2*)(Vs + (mj << 5) + (s << 2));
            float2 f01 = __half22float2(*(__half2*)&hv.x);
            float2 f23 = __half22float2(*(__half2*)&hv.y);
            acc.x = fmaf(pj, f01.x, acc.x);
            acc.y = fmaf(pj, f01.y, acc.y);
            acc.z = fmaf(pj, f23.x, acc.z);
            acc.w = fmaf(pj, f23.y, acc.w);
        }
#pragma unroll
        for (int t = 0; t < 8; t++) {
            unsigned pmj = __shfl_sync(0xffffffffu, pm1, 4 * t + g);
            float    pj  = __uint_as_float(pmj);
            unsigned mj  = pmj & 1023u;
            uint2 hv = *(const uint2*)(Vs + (mj << 5) + (s << 2));
            float2 f01 = __half22float2(*(__half2*)&hv.x);
            float2 f23 = __half22float2(*(__half2*)&hv.y);
            acc.x = fmaf(pj, f01.x, acc.x);
            acc.y = fmaf(pj, f01.y, acc.y);
            acc.z = fmaf(pj, f23.x, acc.z);
            acc.w = fmaf(pj, f23.y, acc.w);
        }

        // reduce denominator over all 32 lanes
#pragma unroll
        for (int off = 16; off; off >>= 1) psum += __shfl_xor_sync(0xffffffffu, psum, off);
        // reduce acc across the 4 edge-groups (lane bits 3..4)
        acc.x += __shfl_xor_sync(0xffffffffu, acc.x, 8);
        acc.y += __shfl_xor_sync(0xffffffffu, acc.y, 8);
        acc.z += __shfl_xor_sync(0xffffffffu, acc.z, 8);
        acc.w += __shfl_xor_sync(0xffffffffu, acc.w, 8);
        acc.x += __shfl_xor_sync(0xffffffffu, acc.x, 16);
        acc.y += __shfl_xor_sync(0xffffffffu, acc.y, 16);
        acc.z += __shfl_xor_sync(0xffffffffu, acc.z, 16);
        acc.w += __shfl_xor_sync(0xffffffffu, acc.w, 16);

        const float inv = 1.f / psum;
        if (g == 0) {
            float4 o;
            o.x = fmaxf(acc.x * inv, 0.f);
            o.y = fmaxf(acc.y * inv, 0.f);
            o.z = fmaxf(acc.z * inv, 0.f);
            o.w = fmaxf(acc.w * inv, 0.f);
            *(float4*)(out + ((size_t)(b * N_ + n)) * OUT_DIM + h * D_ + 4 * s) = o;
        }
    }
}

// ======================= launch =======================
extern "C" void kernel_launch(void* const* d_in, const int* in_sizes, int n_in,
                              void* d_out, int out_size) {
    const float* A   = (const float*)d_in[0];
    const float* X   = (const float*)d_in[1];
    const float* W   = (const float*)d_in[2];
    const float* fc1 = (const float*)d_in[3];
    const float* fc2 = (const float*)d_in[4];
    float* out = (float*)d_out;

    const int smem_gemm = NSTAGE * BUFH * (int)sizeof(__nv_bfloat16);            // 92160 B
    const size_t smem_attn = (size_t)N_ * D_ * 2 + (size_t)N_ * sizeof(float);   // 69632 B
    cudaFuncSetAttribute(k_gemm, cudaFuncAttributeMaxDynamicSharedMemorySize, smem_gemm);
    cudaFuncSetAttribute(k_attn, cudaFuncAttributeMaxDynamicSharedMemorySize, (int)smem_attn);

    k_prep<<<2080, 256>>>(A, X, W);
    k_gemm<<<(ROWS_ / BM) * (OUT_DIM / BN), 256, smem_gemm>>>(fc1, fc2);   // 256 CTAs
    k_attn<<<dim3(RB, H_, B_), 384, smem_attn>>>(out);
}